// round 5
// baseline (speedup 1.0000x reference)
#include <cuda_runtime.h>
#include <math.h>
#include <stdint.h>

#define NIN     12
#define NC      16
#define HID     512
#define KBINS   8
#define BVAL    3.0f
#define LLAYERS 8
#define D_HALF  6
#define DIN     22      // D_HALF + NC
#define DOUT    138     // (3*K-1)*(NIN-D_HALF)
#define SPP     23      // 3*K-1 params per dim
#define TM      16      // rows per CTA
#define NT      256     // threads per CTA
#define HPAD    20      // floats per h_t row (80B: 16B-aligned)

__device__ __forceinline__ float eluf(float v) {
    return v > 0.0f ? v : expm1f(v);
}
__device__ __forceinline__ float softplusf(float v) {
    return v > 20.0f ? v : log1pf(expf(v));
}

// ---- packed f32x2 helpers ----
__device__ __forceinline__ uint64_t bc2(float a) {        // broadcast to both lanes
    uint64_t r;
    asm("mov.b64 %0, {%1, %1};" : "=l"(r) : "f"(a));
    return r;
}
__device__ __forceinline__ void fma2(uint64_t& d, uint64_t a, uint64_t b) {
    asm("fma.rn.f32x2 %0, %1, %2, %0;" : "+l"(d) : "l"(a), "l"(b));
}
__device__ __forceinline__ void upk(uint64_t v, float& lo, float& hi) {
    asm("mov.b64 {%0, %1}, %2;" : "=f"(lo), "=f"(hi) : "l"(v));
}

// GEMM: h_t (transposed act, [HID][TM]) @ W[HID][HID] + b -> elu -> h_t.
// Each thread owns 2 columns (2*tid, 2*tid+1) and ALL 16 rows (8 f32x2 pairs).
// No weight duplication: 256 threads x 2 cols = 512 cols exactly.
__device__ __forceinline__ void gemm_hid_t(const float* __restrict__ W,
                                           const float* __restrict__ bb,
                                           float (*h_t)[HPAD], int tid)
{
    const int j0 = tid * 2;

    uint64_t acc[2][8];
#pragma unroll
    for (int c = 0; c < 2; c++)
#pragma unroll
        for (int p = 0; p < 8; p++) acc[c][p] = 0ull;

#pragma unroll 2
    for (int k = 0; k < HID; k++) {
        float2 w = *(const float2*)(W + (size_t)k * HID + j0);
        uint64_t wp0 = bc2(w.x), wp1 = bc2(w.y);
        ulonglong2 hA = *(const ulonglong2*)&h_t[k][0];   // rows 0..3 (2 pairs)
        ulonglong2 hB = *(const ulonglong2*)&h_t[k][4];   // rows 4..7
        ulonglong2 hC = *(const ulonglong2*)&h_t[k][8];   // rows 8..11
        ulonglong2 hD = *(const ulonglong2*)&h_t[k][12];  // rows 12..15
        fma2(acc[0][0], hA.x, wp0); fma2(acc[1][0], hA.x, wp1);
        fma2(acc[0][1], hA.y, wp0); fma2(acc[1][1], hA.y, wp1);
        fma2(acc[0][2], hB.x, wp0); fma2(acc[1][2], hB.x, wp1);
        fma2(acc[0][3], hB.y, wp0); fma2(acc[1][3], hB.y, wp1);
        fma2(acc[0][4], hC.x, wp0); fma2(acc[1][4], hC.x, wp1);
        fma2(acc[0][5], hC.y, wp0); fma2(acc[1][5], hC.y, wp1);
        fma2(acc[0][6], hD.x, wp0); fma2(acc[1][6], hD.x, wp1);
        fma2(acc[0][7], hD.y, wp0); fma2(acc[1][7], hD.y, wp1);
    }

    float2 bv2 = *(const float2*)(bb + j0);
    __syncthreads();   // all reads of h_t complete before overwrite
#pragma unroll
    for (int c = 0; c < 2; c++) {
        float bvc = c ? bv2.y : bv2.x;
        float v[16];
#pragma unroll
        for (int p = 0; p < 8; p++) upk(acc[c][p], v[2 * p], v[2 * p + 1]);
#pragma unroll
        for (int q = 0; q < 4; q++) {
            float4 o;
            o.x = eluf(v[4 * q + 0] + bvc);
            o.y = eluf(v[4 * q + 1] + bvc);
            o.z = eluf(v[4 * q + 2] + bvc);
            o.w = eluf(v[4 * q + 3] + bvc);
            *(float4*)&h_t[j0 + c][4 * q] = o;
        }
    }
    __syncthreads();
}

__global__ __launch_bounds__(NT, 4) void flow_kernel(
    const float* __restrict__ z,  const float* __restrict__ c,
    const float* __restrict__ W0, const float* __restrict__ b0,
    const float* __restrict__ W1, const float* __restrict__ b1,
    const float* __restrict__ W2, const float* __restrict__ b2,
    const float* __restrict__ W3, const float* __restrict__ b3,
    const int*   __restrict__ perms,
    float* __restrict__ out, int n)
{
    __shared__ float h_t[HID][HPAD];        // 40 KB transposed activations
    __shared__ float out_s[TM][DOUT + 2];   // spline params
    __shared__ float inp_t[DIN][TM];        // transposed MLP input
    __shared__ float x_s[TM][NIN];
    __shared__ float xt_s[TM][NIN];
    __shared__ float c_s[TM][NC];
    __shared__ float ld_s[TM];
    __shared__ float lad_s[TM][D_HALF];
    __shared__ int   perm_s[(LLAYERS - 1) * NIN];

    const int tid  = threadIdx.x;
    const int row0 = blockIdx.x * TM;

    for (int i = tid; i < TM * NIN; i += NT) x_s[i / NIN][i % NIN] = z[(size_t)row0 * NIN + i];
    for (int i = tid; i < TM * NC;  i += NT) c_s[i / NC][i % NC]   = c[(size_t)row0 * NC + i];
    if (tid < TM) ld_s[tid] = 0.0f;
    if (tid < (LLAYERS - 1) * NIN) perm_s[tid] = perms[tid];
    __syncthreads();

    for (int layer = 0; layer < LLAYERS; layer++) {
        // ---- build inp_t = concat(x1, c)^T  (DIN*TM = 352 > NT: strided) ----
        for (int i = tid; i < DIN * TM; i += NT) {
            int k = i / TM, m = i % TM;
            inp_t[k][m] = (k < D_HALF) ? x_s[m][k] : c_s[m][k - D_HALF];
        }
        __syncthreads();

        // ---- GEMM0: inp[TM][22] @ W0 -> elu -> h_t (small; scalar) ----
        {
            const float* W  = W0 + (size_t)layer * DIN * HID;
            const float* bb = b0 + (size_t)layer * HID;
            const int j0 = tid * 2;
            float a[16][2];
#pragma unroll
            for (int m = 0; m < 16; m++) { a[m][0] = 0.0f; a[m][1] = 0.0f; }
            for (int k = 0; k < DIN; k++) {
                float2 w = *(const float2*)(W + (size_t)k * HID + j0);
#pragma unroll
                for (int m = 0; m < 16; m++) {
                    float hv = inp_t[k][m];
                    a[m][0] = fmaf(hv, w.x, a[m][0]);
                    a[m][1] = fmaf(hv, w.y, a[m][1]);
                }
            }
            float2 bv2 = *(const float2*)(bb + j0);
#pragma unroll
            for (int cc = 0; cc < 2; cc++) {
                float bvc = cc ? bv2.y : bv2.x;
#pragma unroll
                for (int q = 0; q < 4; q++) {
                    float4 o;
                    o.x = eluf(a[4 * q + 0][cc] + bvc);
                    o.y = eluf(a[4 * q + 1][cc] + bvc);
                    o.z = eluf(a[4 * q + 2][cc] + bvc);
                    o.w = eluf(a[4 * q + 3][cc] + bvc);
                    *(float4*)&h_t[j0 + cc][4 * q] = o;
                }
            }
            __syncthreads();
        }

        // ---- GEMM1, GEMM2: 512x512, packed f32x2, transposed layout ----
        gemm_hid_t(W1 + (size_t)layer * HID * HID, b1 + (size_t)layer * HID, h_t, tid);
        gemm_hid_t(W2 + (size_t)layer * HID * HID, b2 + (size_t)layer * HID, h_t, tid);

        // ---- GEMM3: h[TM][512] @ W3[512][138] + b3 -> out_s ----
        {
            const float* W  = W3 + (size_t)layer * HID * DOUT;
            const float* bb = b3 + (size_t)layer * DOUT;
            const int jl = tid & 127;
            const int rb = (tid >> 7) * 8;       // 2 groups of 8 rows (4 pairs)
            const bool has2 = jl < (DOUT - 128); // 10 extra columns
            uint64_t a1[4], a2[4];
#pragma unroll
            for (int p = 0; p < 4; p++) { a1[p] = 0ull; a2[p] = 0ull; }
#pragma unroll 2
            for (int k = 0; k < HID; k++) {
                const float* Wk = W + (size_t)k * DOUT;
                uint64_t wp = bc2(Wk[jl]);
                ulonglong2 hA = *(const ulonglong2*)&h_t[k][rb];
                ulonglong2 hB = *(const ulonglong2*)&h_t[k][rb + 4];
                fma2(a1[0], hA.x, wp); fma2(a1[1], hA.y, wp);
                fma2(a1[2], hB.x, wp); fma2(a1[3], hB.y, wp);
                if (has2) {
                    uint64_t wp2 = bc2(Wk[128 + jl]);
                    fma2(a2[0], hA.x, wp2); fma2(a2[1], hA.y, wp2);
                    fma2(a2[2], hB.x, wp2); fma2(a2[3], hB.y, wp2);
                }
            }
            float bx  = bb[jl];
            float bx2 = has2 ? bb[128 + jl] : 0.0f;
#pragma unroll
            for (int p = 0; p < 4; p++) {
                float lo, hi;
                upk(a1[p], lo, hi);
                out_s[rb + 2 * p][jl]     = lo + bx;
                out_s[rb + 2 * p + 1][jl] = hi + bx;
                if (has2) {
                    upk(a2[p], lo, hi);
                    out_s[rb + 2 * p][128 + jl]     = lo + bx2;
                    out_s[rb + 2 * p + 1][128 + jl] = hi + bx2;
                }
            }
            __syncthreads();
        }

        // ---- RQ spline: one thread per (row, dim) ----
        if (tid < TM * D_HALF) {
            const int m = tid / D_HALF, d = tid % D_HALF;
            const float* p = &out_s[m][d * SPP];

            float e[KBINS];
            float mx = p[0];
#pragma unroll
            for (int i = 1; i < KBINS; i++) mx = fmaxf(mx, p[i]);
            float s = 0.0f;
#pragma unroll
            for (int i = 0; i < KBINS; i++) { e[i] = expf(p[i] - mx); s += e[i]; }
            float inv = 1.0f / s;
            float cw[KBINS + 1];
            cw[0] = -BVAL;
            {
                float run = 0.0f;
#pragma unroll
                for (int i = 0; i < KBINS - 1; i++) {
                    run += 0.001f + 0.992f * e[i] * inv;
                    cw[i + 1] = 2.0f * BVAL * run - BVAL;
                }
            }
            cw[KBINS] = BVAL;

            mx = p[KBINS];
#pragma unroll
            for (int i = 1; i < KBINS; i++) mx = fmaxf(mx, p[KBINS + i]);
            s = 0.0f;
#pragma unroll
            for (int i = 0; i < KBINS; i++) { e[i] = expf(p[KBINS + i] - mx); s += e[i]; }
            inv = 1.0f / s;
            float ch[KBINS + 1];
            ch[0] = -BVAL;
            {
                float run = 0.0f;
#pragma unroll
                for (int i = 0; i < KBINS - 1; i++) {
                    run += 0.001f + 0.992f * e[i] * inv;
                    ch[i + 1] = 2.0f * BVAL * run - BVAL;
                }
            }
            ch[KBINS] = BVAL;

            float dv[KBINS + 1];
            dv[0] = 1.0f; dv[KBINS] = 1.0f;
#pragma unroll
            for (int i = 1; i < KBINS; i++)
                dv[i] = 0.001f + softplusf(p[2 * KBINS + i - 1]);

            float x  = x_s[m][D_HALF + d];
            float xc = fminf(fmaxf(x, -BVAL), BVAL);
            int idx = 0;
#pragma unroll
            for (int i = 1; i < KBINS; i++) idx += (xc >= cw[i]) ? 1 : 0;

            float icw = cw[idx], iw = cw[idx + 1] - cw[idx];
            float ich = ch[idx], ih = ch[idx + 1] - ch[idx];
            float delta = ih / iw;
            float d0 = dv[idx], d1 = dv[idx + 1];
            float th  = (xc - icw) / iw;
            float t1m = th * (1.0f - th);
            float num = ih * (delta * th * th + d0 * t1m);
            float den = delta + (d0 + d1 - 2.0f * delta) * t1m;
            float o = ich + num / den;
            float omt = 1.0f - th;
            float dnum = delta * delta * (d1 * th * th + 2.0f * delta * t1m + d0 * omt * omt);
            float lad = logf(dnum) - 2.0f * logf(den);
            bool inside = (x >= -BVAL) && (x <= BVAL);
            x_s[m][D_HALF + d] = inside ? o : x;
            lad_s[m][d] = inside ? lad : 0.0f;
        }
        __syncthreads();

        if (tid < TM) {
            float acc = ld_s[tid];
#pragma unroll
            for (int d = 0; d < D_HALF; d++) acc += lad_s[tid][d];
            ld_s[tid] = acc;
        }

        // ---- permutation ----
        if (layer < LLAYERS - 1) {
            if (tid < TM * NIN) {
                int m = tid / NIN, j = tid % NIN;
                xt_s[m][j] = x_s[m][perm_s[layer * NIN + j]];
            }
            __syncthreads();
            if (tid < TM * NIN) {
                int m = tid / NIN, j = tid % NIN;
                x_s[m][j] = xt_s[m][j];
            }
        }
        __syncthreads();
    }

    // ---- write outputs: x [N,12] then total_ld [N] ----
    for (int i = tid; i < TM * NIN; i += NT)
        out[(size_t)row0 * NIN + i] = x_s[i / NIN][i % NIN];
    if (tid < TM)
        out[(size_t)n * NIN + row0 + tid] = ld_s[tid];
}

extern "C" void kernel_launch(void* const* d_in, const int* in_sizes, int n_in,
                              void* d_out, int out_size)
{
    const float* z     = (const float*)d_in[0];
    const float* c     = (const float*)d_in[1];
    const float* W0    = (const float*)d_in[2];
    const float* b0    = (const float*)d_in[3];
    const float* W1    = (const float*)d_in[4];
    const float* b1    = (const float*)d_in[5];
    const float* W2    = (const float*)d_in[6];
    const float* b2    = (const float*)d_in[7];
    const float* W3    = (const float*)d_in[8];
    const float* b3    = (const float*)d_in[9];
    const int*   perms = (const int*)d_in[10];

    int n = in_sizes[0] / NIN;
    int grid = (n + TM - 1) / TM;
    flow_kernel<<<grid, NT>>>(z, c, W0, b0, W1, b1, W2, b2, W3, b3, perms,
                              (float*)d_out, n);
}

// round 7
// speedup vs baseline: 1.7417x; 1.7417x over previous
#include <cuda_runtime.h>
#include <cuda_bf16.h>
#include <math.h>
#include <stdint.h>

#define LAYERS  8
#define MTOT    32768
#define MT      128
#define MTILES  (MTOT / MT)      // 256
#define HID     512
#define DINR    22
#define K0      64               // padded K for GEMM0
#define DOUT    138
#define DOUTP   160              // padded N for GEMM3
#define KBINS   8
#define BVAL    3.0f
#define D_HALF  6
#define SPP     23

// ---------------- device global scratch ----------------
__device__ __nv_bfloat16 g_w0h[LAYERS * K0 * 512];
__device__ __nv_bfloat16 g_w0l[LAYERS * K0 * 512];
__device__ __nv_bfloat16 g_w1h[LAYERS * 512 * 512];
__device__ __nv_bfloat16 g_w1l[LAYERS * 512 * 512];
__device__ __nv_bfloat16 g_w2h[LAYERS * 512 * 512];
__device__ __nv_bfloat16 g_w2l[LAYERS * 512 * 512];
__device__ __nv_bfloat16 g_w3h[LAYERS * 512 * DOUTP];
__device__ __nv_bfloat16 g_w3l[LAYERS * 512 * DOUTP];
__device__ __nv_bfloat16 g_a0h[MTOT * K0];
__device__ __nv_bfloat16 g_a0l[MTOT * K0];
__device__ __nv_bfloat16 g_bAh[MTOT * HID];
__device__ __nv_bfloat16 g_bAl[MTOT * HID];
__device__ __nv_bfloat16 g_bBh[MTOT * HID];
__device__ __nv_bfloat16 g_bBl[MTOT * HID];
__device__ float g_params[(size_t)MTOT * DOUTP];
__device__ float g_x[MTOT * 12];
__device__ float g_ld[MTOT];

// ---------------- helpers ----------------
__device__ __forceinline__ float eluf(float v) { return v > 0.0f ? v : expm1f(v); }
__device__ __forceinline__ float softplusf(float v) { return v > 20.0f ? v : log1pf(expf(v)); }

__device__ __forceinline__ uint32_t smem_u32(const void* p) {
    uint32_t a;
    asm("{ .reg .u64 t; cvta.to.shared.u64 t, %1; cvt.u32.u64 %0, t; }" : "=r"(a) : "l"(p));
    return a;
}
__device__ __forceinline__ uint32_t pkbf(__nv_bfloat16 a, __nv_bfloat16 b) {
    return (uint32_t)__bfloat16_as_ushort(a) | ((uint32_t)__bfloat16_as_ushort(b) << 16);
}
__device__ __forceinline__ void cp16(uint32_t sdst, const void* gsrc) {
    asm volatile("cp.async.cg.shared.global [%0], [%1], 16;" :: "r"(sdst), "l"(gsrc));
}
__device__ __forceinline__ void ldsm4(uint32_t* r, uint32_t a) {
    asm volatile("ldmatrix.sync.aligned.m8n8.x4.shared.b16 {%0,%1,%2,%3}, [%4];"
                 : "=r"(r[0]), "=r"(r[1]), "=r"(r[2]), "=r"(r[3]) : "r"(a));
}
__device__ __forceinline__ void ldsm4t(uint32_t* r, uint32_t a) {
    asm volatile("ldmatrix.sync.aligned.m8n8.x4.trans.shared.b16 {%0,%1,%2,%3}, [%4];"
                 : "=r"(r[0]), "=r"(r[1]), "=r"(r[2]), "=r"(r[3]) : "r"(a));
}
__device__ __forceinline__ void mma_bf16(float* d, const uint32_t* a, uint32_t b0, uint32_t b1) {
    asm volatile(
        "mma.sync.aligned.m16n8k16.row.col.f32.bf16.bf16.f32 "
        "{%0,%1,%2,%3}, {%4,%5,%6,%7}, {%8,%9}, {%0,%1,%2,%3};"
        : "+f"(d[0]), "+f"(d[1]), "+f"(d[2]), "+f"(d[3])
        : "r"(a[0]), "r"(a[1]), "r"(a[2]), "r"(a[3]), "r"(b0), "r"(b1));
}

// ---------------- prep: weights -> bf16 hi/lo k-major blobs ----------------
__global__ void prep_weights(const float* __restrict__ W0, const float* __restrict__ W1,
                             const float* __restrict__ W2, const float* __restrict__ W3) {
    const long N0 = (long)LAYERS * K0 * 512;     // 262144
    const long N1 = (long)LAYERS * 512 * 512;    // 2097152
    const long N3 = (long)LAYERS * 512 * DOUTP;  // 655360
    const long TOT = N0 + 2 * N1 + N3;
    for (long i = (long)blockIdx.x * blockDim.x + threadIdx.x; i < TOT;
         i += (long)gridDim.x * blockDim.x) {
        float v; long dst; __nv_bfloat16 *ph, *pl;
        if (i < N0) {
            long l = i / (K0 * 512), r = i % (K0 * 512);
            int k = (int)(r / 512), n = (int)(r % 512);
            v = (k < DINR) ? W0[(l * DINR + k) * 512 + n] : 0.0f;
            dst = i; ph = g_w0h; pl = g_w0l;
        } else if (i < N0 + N1) {
            long e = i - N0;
            v = W1[e]; dst = e; ph = g_w1h; pl = g_w1l;
        } else if (i < N0 + 2 * N1) {
            long e = i - N0 - N1;
            v = W2[e]; dst = e; ph = g_w2h; pl = g_w2l;
        } else {
            long e = i - N0 - 2 * N1;
            long l = e / (512L * DOUTP), r = e % (512L * DOUTP);
            int k = (int)(r / DOUTP), n = (int)(r % DOUTP);
            v = (n < DOUT) ? W3[(l * 512 + k) * DOUT + n] : 0.0f;
            dst = e; ph = g_w3h; pl = g_w3l;
        }
        __nv_bfloat16 hi = __float2bfloat16(v);
        __nv_bfloat16 lo = __float2bfloat16(v - __bfloat162float(hi));
        ph[dst] = hi; pl[dst] = lo;
    }
}

__global__ void init_state(const float* __restrict__ z) {
    int m = blockIdx.x * blockDim.x + threadIdx.x;
    if (m >= MTOT) return;
    g_ld[m] = 0.0f;
#pragma unroll
    for (int j = 0; j < 12; j++) g_x[m * 12 + j] = z[m * 12 + j];
}

// concat: [x1 | c | 0pad] -> g_a0 hi/lo row-major [m][64]
__global__ void concat_kernel(const float* __restrict__ c) {
    int m = blockIdx.x * blockDim.x + threadIdx.x;
    if (m >= MTOT) return;
    uint32_t* oh = (uint32_t*)&g_a0h[m * K0];
    uint32_t* ol = (uint32_t*)&g_a0l[m * K0];
#pragma unroll
    for (int q = 0; q < 32; q++) {
        __nv_bfloat16 h2[2], l2[2];
#pragma unroll
        for (int t = 0; t < 2; t++) {
            int k = q * 2 + t;
            float v = (k < D_HALF) ? g_x[m * 12 + k]
                      : (k < DINR ? c[m * 16 + (k - D_HALF)] : 0.0f);
            h2[t] = __float2bfloat16(v);
            l2[t] = __float2bfloat16(v - __bfloat162float(h2[t]));
        }
        oh[q] = pkbf(h2[0], h2[1]);
        ol[q] = pkbf(l2[0], l2[1]);
    }
}

// ---------------- GEMM via mma.sync bf16x3 ----------------
// A: [MTOT][LDA] bf16 hi/lo row-major. W blob: [KTOT][NTN] hi/lo k-major.
// MODE 0: ELU(D+bias) -> split -> bf16 hi/lo out (row-major [m][512])
// MODE 1: D+bias fp32 -> g_params [m][DOUTP]
template<int NCN, int NTN, int KTOT, int LDA, int MODE>
__global__ void __launch_bounds__(256) gemm_mma(int asel, int osel, int wsel, int layer,
                                                const float* __restrict__ bias, int bias_n)
{
    extern __shared__ char smem[];
    constexpr int SA_STR = 72;                     // bf16 elems; 144B rows (conflict-free)
    constexpr int SW_STR = NCN + 8;                // 136 -> 272B, 168 -> 336B
    constexpr int A_BYTES = 128 * SA_STR * 2;      // 18432
    constexpr int W_BYTES = 64 * SW_STR * 2;
    constexpr int SM_AH = 0;
    constexpr int SM_AL = A_BYTES;
    constexpr int SM_WH = 2 * A_BYTES;
    constexpr int SM_WL = 2 * A_BYTES + W_BYTES;
    constexpr int NTILE = NCN / 8;
    constexpr int WSEG = NCN / 8;                  // 16B segs per W row

    const int tid = threadIdx.x, wid = tid >> 5, lane = tid & 31;
    const int tile = blockIdx.x;
    uint32_t sb = smem_u32(smem);

    const __nv_bfloat16* Ah = (asel == 0) ? g_a0h : (asel == 1 ? g_bAh : g_bBh);
    const __nv_bfloat16* Al = (asel == 0) ? g_a0l : (asel == 1 ? g_bAl : g_bBl);
    const __nv_bfloat16 *Wh, *Wl;
    if      (wsel == 0) { Wh = g_w0h + (size_t)layer * K0 * 512;    Wl = g_w0l + (size_t)layer * K0 * 512; }
    else if (wsel == 1) { Wh = g_w1h + (size_t)layer * 512 * 512;   Wl = g_w1l + (size_t)layer * 512 * 512; }
    else if (wsel == 2) { Wh = g_w2h + (size_t)layer * 512 * 512;   Wl = g_w2l + (size_t)layer * 512 * 512; }
    else                { Wh = g_w3h + (size_t)layer * 512 * DOUTP; Wl = g_w3l + (size_t)layer * 512 * DOUTP; }

    const char* agh = (const char*)(Ah + (size_t)tile * MT * LDA);
    const char* agl = (const char*)(Al + (size_t)tile * MT * LDA);

    // ldmatrix lane addresses
    const uint32_t a_off = (uint32_t)((wid * 16 + (lane & 15)) * SA_STR * 2 + (lane >> 4) * 16);
    const uint32_t b_off = (uint32_t)((lane & 15) * SW_STR * 2 + (lane >> 4) * 16);

    for (int nc = 0; nc < NTN / NCN; nc++) {
        float acc[NTILE][4];
#pragma unroll
        for (int t = 0; t < NTILE; t++)
#pragma unroll
            for (int q = 0; q < 4; q++) acc[t][q] = 0.0f;

        for (int kc = 0; kc < KTOT / 64; kc++) {
            __syncthreads();   // previous chunk's ldmatrix reads complete
            // stage A chunk [128][64]
            for (int i = tid; i < 1024; i += 256) {
                int r = i >> 3, seg = i & 7;
                uint32_t so = (uint32_t)(r * SA_STR * 2 + seg * 16);
                size_t go = (size_t)r * LDA * 2 + (size_t)kc * 128 + seg * 16;
                cp16(sb + SM_AH + so, agh + go);
                cp16(sb + SM_AL + so, agl + go);
            }
            // stage W chunk [64][NCN]
            {
                const char* wgh = (const char*)Wh + ((size_t)kc * 64 * NTN + (size_t)nc * NCN) * 2;
                const char* wgl = (const char*)Wl + ((size_t)kc * 64 * NTN + (size_t)nc * NCN) * 2;
                for (int i = tid; i < 64 * WSEG; i += 256) {
                    int r = i / WSEG, seg = i % WSEG;
                    uint32_t so = (uint32_t)(r * SW_STR * 2 + seg * 16);
                    size_t go = (size_t)r * NTN * 2 + seg * 16;
                    cp16(sb + SM_WH + so, wgh + go);
                    cp16(sb + SM_WL + so, wgl + go);
                }
            }
            asm volatile("cp.async.commit_group;" ::: "memory");
            asm volatile("cp.async.wait_group 0;" ::: "memory");
            __syncthreads();

#pragma unroll
            for (int s = 0; s < 4; s++) {
                uint32_t ahr[4], alr[4];
                ldsm4(ahr, sb + SM_AH + a_off + s * 32);
                ldsm4(alr, sb + SM_AL + a_off + s * 32);
                uint32_t brow = b_off + (uint32_t)(s * 16 * SW_STR * 2);
#pragma unroll
                for (int jb = 0; jb < NTILE / 2; jb++) {
                    uint32_t bh[4], bl[4];
                    ldsm4t(bh, sb + SM_WH + brow + jb * 32);
                    ldsm4t(bl, sb + SM_WL + brow + jb * 32);
                    mma_bf16(acc[2 * jb],     ahr, bh[0], bh[1]);
                    mma_bf16(acc[2 * jb],     ahr, bl[0], bl[1]);
                    mma_bf16(acc[2 * jb],     alr, bh[0], bh[1]);
                    mma_bf16(acc[2 * jb + 1], ahr, bh[2], bh[3]);
                    mma_bf16(acc[2 * jb + 1], ahr, bl[2], bl[3]);
                    mma_bf16(acc[2 * jb + 1], alr, bh[2], bh[3]);
                }
            }
        }

        // ---- epilogue for this n-chunk ----
        const int r0 = tile * MT + wid * 16 + (lane >> 2);
        const int cbase = nc * NCN + (lane & 3) * 2;
        if (MODE == 0) {
            __nv_bfloat16* Oh = (osel == 1) ? g_bAh : g_bBh;
            __nv_bfloat16* Ol = (osel == 1) ? g_bAl : g_bBl;
#pragma unroll
            for (int t = 0; t < NTILE; t++) {
                int col = cbase + t * 8;
                float b0 = __ldg(&bias[col]), b1 = __ldg(&bias[col + 1]);
#pragma unroll
                for (int h = 0; h < 2; h++) {
                    int row = r0 + h * 8;
                    float v0 = eluf(acc[t][2 * h] + b0);
                    float v1 = eluf(acc[t][2 * h + 1] + b1);
                    __nv_bfloat16 h0 = __float2bfloat16(v0);
                    __nv_bfloat16 h1 = __float2bfloat16(v1);
                    __nv_bfloat16 l0 = __float2bfloat16(v0 - __bfloat162float(h0));
                    __nv_bfloat16 l1 = __float2bfloat16(v1 - __bfloat162float(h1));
                    *(uint32_t*)&Oh[(size_t)row * HID + col] = pkbf(h0, h1);
                    *(uint32_t*)&Ol[(size_t)row * HID + col] = pkbf(l0, l1);
                }
            }
        } else {
#pragma unroll
            for (int t = 0; t < NTILE; t++) {
                int col = cbase + t * 8;
                float b0 = (col < bias_n) ? __ldg(&bias[col]) : 0.0f;
                float b1 = (col + 1 < bias_n) ? __ldg(&bias[col + 1]) : 0.0f;
#pragma unroll
                for (int h = 0; h < 2; h++) {
                    int row = r0 + h * 8;
                    g_params[(size_t)row * DOUTP + col]     = acc[t][2 * h] + b0;
                    g_params[(size_t)row * DOUTP + col + 1] = acc[t][2 * h + 1] + b1;
                }
            }
        }
    }
}

// ---------------- spline + permutation ----------------
__global__ void spline_kernel(const int* __restrict__ perms, int layer) {
    int m = blockIdx.x * blockDim.x + threadIdx.x;
    if (m >= MTOT) return;
    const float* pall = &g_params[(size_t)m * DOUTP];
    float cat[12];
#pragma unroll
    for (int j = 0; j < D_HALF; j++) cat[j] = g_x[m * 12 + j];
    float ldsum = 0.0f;
#pragma unroll
    for (int d = 0; d < D_HALF; d++) {
        const float* p = pall + d * SPP;
        float e[KBINS];
        float mx = p[0];
#pragma unroll
        for (int i = 1; i < KBINS; i++) mx = fmaxf(mx, p[i]);
        float s = 0.0f;
#pragma unroll
        for (int i = 0; i < KBINS; i++) { e[i] = expf(p[i] - mx); s += e[i]; }
        float inv = 1.0f / s;
        float cw[KBINS + 1];
        cw[0] = -BVAL;
        {
            float run = 0.0f;
#pragma unroll
            for (int i = 0; i < KBINS - 1; i++) {
                run += 0.001f + 0.992f * e[i] * inv;
                cw[i + 1] = 2.0f * BVAL * run - BVAL;
            }
        }
        cw[KBINS] = BVAL;
        mx = p[KBINS];
#pragma unroll
        for (int i = 1; i < KBINS; i++) mx = fmaxf(mx, p[KBINS + i]);
        s = 0.0f;
#pragma unroll
        for (int i = 0; i < KBINS; i++) { e[i] = expf(p[KBINS + i] - mx); s += e[i]; }
        inv = 1.0f / s;
        float chn[KBINS + 1];
        chn[0] = -BVAL;
        {
            float run = 0.0f;
#pragma unroll
            for (int i = 0; i < KBINS - 1; i++) {
                run += 0.001f + 0.992f * e[i] * inv;
                chn[i + 1] = 2.0f * BVAL * run - BVAL;
            }
        }
        chn[KBINS] = BVAL;
        float dv[KBINS + 1];
        dv[0] = 1.0f; dv[KBINS] = 1.0f;
#pragma unroll
        for (int i = 1; i < KBINS; i++) dv[i] = 0.001f + softplusf(p[2 * KBINS + i - 1]);

        float x = g_x[m * 12 + D_HALF + d];
        float xc = fminf(fmaxf(x, -BVAL), BVAL);
        int idx = 0;
#pragma unroll
        for (int i = 1; i < KBINS; i++) idx += (xc >= cw[i]) ? 1 : 0;
        float icw = cw[idx], iw = cw[idx + 1] - cw[idx];
        float ich = chn[idx], ih = chn[idx + 1] - chn[idx];
        float delta = ih / iw;
        float d0 = dv[idx], d1 = dv[idx + 1];
        float th = (xc - icw) / iw;
        float t1m = th * (1.0f - th);
        float num = ih * (delta * th * th + d0 * t1m);
        float den = delta + (d0 + d1 - 2.0f * delta) * t1m;
        float o = ich + num / den;
        float omt = 1.0f - th;
        float dnum = delta * delta * (d1 * th * th + 2.0f * delta * t1m + d0 * omt * omt);
        float lad = logf(dnum) - 2.0f * logf(den);
        bool inside = (x >= -BVAL) && (x <= BVAL);
        cat[D_HALF + d] = inside ? o : x;
        ldsum += inside ? lad : 0.0f;
    }
    g_ld[m] += ldsum;
    float xn[12];
    if (layer < LAYERS - 1) {
#pragma unroll
        for (int j = 0; j < 12; j++) xn[j] = cat[perms[layer * 12 + j]];
    } else {
#pragma unroll
        for (int j = 0; j < 12; j++) xn[j] = cat[j];
    }
#pragma unroll
    for (int j = 0; j < 12; j++) g_x[m * 12 + j] = xn[j];
}

__global__ void final_kernel(float* __restrict__ out) {
    int m = blockIdx.x * blockDim.x + threadIdx.x;
    if (m >= MTOT) return;
#pragma unroll
    for (int j = 0; j < 12; j++) out[m * 12 + j] = g_x[m * 12 + j];
    out[(size_t)MTOT * 12 + m] = g_ld[m];
}

// ---------------- host ----------------
extern "C" void kernel_launch(void* const* d_in, const int* in_sizes, int n_in,
                              void* d_out, int out_size)
{
    const float* z  = (const float*)d_in[0];
    const float* c  = (const float*)d_in[1];
    const float* W0 = (const float*)d_in[2];
    const float* b0 = (const float*)d_in[3];
    const float* W1 = (const float*)d_in[4];
    const float* b1 = (const float*)d_in[5];
    const float* W2 = (const float*)d_in[6];
    const float* b2 = (const float*)d_in[7];
    const float* W3 = (const float*)d_in[8];
    const float* b3 = (const float*)d_in[9];
    const int* perms = (const int*)d_in[10];

    // smem sizes
    const int SM_G12 = 2 * (128 * 72 * 2) + 2 * (64 * 136 * 2);   // 71,680
    const int SM_G3  = 2 * (128 * 72 * 2) + 2 * (64 * 168 * 2);   // 79,872
    cudaFuncSetAttribute(gemm_mma<128, 512,  64,  64, 0>, cudaFuncAttributeMaxDynamicSharedMemorySize, SM_G12);
    cudaFuncSetAttribute(gemm_mma<128, 512, 512, 512, 0>, cudaFuncAttributeMaxDynamicSharedMemorySize, SM_G12);
    cudaFuncSetAttribute(gemm_mma<160, 160, 512, 512, 1>, cudaFuncAttributeMaxDynamicSharedMemorySize, SM_G3);

    prep_weights<<<2048, 256>>>(W0, W1, W2, W3);
    init_state<<<MTOT / 256, 256>>>(z);
    for (int l = 0; l < LAYERS; l++) {
        concat_kernel<<<MTOT / 256, 256>>>(c);
        gemm_mma<128, 512,  64,  64, 0><<<MTILES, 256, SM_G12>>>(0, 1, 0, l, b0 + l * 512, 512);
        gemm_mma<128, 512, 512, 512, 0><<<MTILES, 256, SM_G12>>>(1, 2, 1, l, b1 + l * 512, 512);
        gemm_mma<128, 512, 512, 512, 0><<<MTILES, 256, SM_G12>>>(2, 1, 2, l, b2 + l * 512, 512);
        gemm_mma<160, 160, 512, 512, 1><<<MTILES, 256, SM_G3>>>(1, 0, 3, l, b3 + l * DOUT, DOUT);
        spline_kernel<<<MTOT / 256, 256>>>(perms, l);
    }
    final_kernel<<<MTOT / 256, 256>>>((float*)d_out);
}

// round 8
// speedup vs baseline: 2.1244x; 1.2197x over previous
#include <cuda_runtime.h>
#include <cuda_bf16.h>
#include <math.h>
#include <stdint.h>

#define LAYERS  8
#define MTOT    32768
#define MT      128
#define MTILES  (MTOT / MT)      // 256
#define HID     512
#define DINR    22
#define K0      64               // padded K for GEMM0
#define DOUT    138
#define DOUTP   160              // padded N for GEMM3
#define KBINS   8
#define BVAL    3.0f
#define D_HALF  6
#define SPP     23

// ---------------- device global scratch ----------------
__device__ __nv_bfloat16 g_w0h[LAYERS * K0 * 512];
__device__ __nv_bfloat16 g_w0l[LAYERS * K0 * 512];
__device__ __nv_bfloat16 g_w1h[LAYERS * 512 * 512];
__device__ __nv_bfloat16 g_w1l[LAYERS * 512 * 512];
__device__ __nv_bfloat16 g_w2h[LAYERS * 512 * 512];
__device__ __nv_bfloat16 g_w2l[LAYERS * 512 * 512];
__device__ __nv_bfloat16 g_w3h[LAYERS * 512 * DOUTP];
__device__ __nv_bfloat16 g_w3l[LAYERS * 512 * DOUTP];
__device__ __nv_bfloat16 g_a0h[MTOT * K0];
__device__ __nv_bfloat16 g_a0l[MTOT * K0];
__device__ __nv_bfloat16 g_bAh[MTOT * HID];
__device__ __nv_bfloat16 g_bAl[MTOT * HID];
__device__ __nv_bfloat16 g_bBh[MTOT * HID];
__device__ __nv_bfloat16 g_bBl[MTOT * HID];
__device__ float g_params[(size_t)MTOT * DOUTP];
__device__ float g_x[MTOT * 12];
__device__ float g_ld[MTOT];

// ---------------- helpers ----------------
__device__ __forceinline__ float eluf(float v) { return v > 0.0f ? v : expm1f(v); }
__device__ __forceinline__ float softplusf(float v) { return v > 20.0f ? v : log1pf(expf(v)); }

__device__ __forceinline__ uint32_t smem_u32(const void* p) {
    uint32_t a;
    asm("{ .reg .u64 t; cvta.to.shared.u64 t, %1; cvt.u32.u64 %0, t; }" : "=r"(a) : "l"(p));
    return a;
}
__device__ __forceinline__ uint32_t pkbf(__nv_bfloat16 a, __nv_bfloat16 b) {
    return (uint32_t)__bfloat16_as_ushort(a) | ((uint32_t)__bfloat16_as_ushort(b) << 16);
}
__device__ __forceinline__ void cp16(uint32_t sdst, const void* gsrc) {
    asm volatile("cp.async.cg.shared.global [%0], [%1], 16;" :: "r"(sdst), "l"(gsrc));
}
__device__ __forceinline__ void ldsm4(uint32_t* r, uint32_t a) {
    asm volatile("ldmatrix.sync.aligned.m8n8.x4.shared.b16 {%0,%1,%2,%3}, [%4];"
                 : "=r"(r[0]), "=r"(r[1]), "=r"(r[2]), "=r"(r[3]) : "r"(a));
}
__device__ __forceinline__ void ldsm4t(uint32_t* r, uint32_t a) {
    asm volatile("ldmatrix.sync.aligned.m8n8.x4.trans.shared.b16 {%0,%1,%2,%3}, [%4];"
                 : "=r"(r[0]), "=r"(r[1]), "=r"(r[2]), "=r"(r[3]) : "r"(a));
}
__device__ __forceinline__ void mma_bf16(float* d, const uint32_t* a, uint32_t b0, uint32_t b1) {
    asm volatile(
        "mma.sync.aligned.m16n8k16.row.col.f32.bf16.bf16.f32 "
        "{%0,%1,%2,%3}, {%4,%5,%6,%7}, {%8,%9}, {%0,%1,%2,%3};"
        : "+f"(d[0]), "+f"(d[1]), "+f"(d[2]), "+f"(d[3])
        : "r"(a[0]), "r"(a[1]), "r"(a[2]), "r"(a[3]), "r"(b0), "r"(b1));
}

// ---------------- prep: weights -> bf16 hi/lo k-major blobs ----------------
__global__ void prep_weights(const float* __restrict__ W0, const float* __restrict__ W1,
                             const float* __restrict__ W2, const float* __restrict__ W3) {
    const long N0 = (long)LAYERS * K0 * 512;
    const long N1 = (long)LAYERS * 512 * 512;
    const long N3 = (long)LAYERS * 512 * DOUTP;
    const long TOT = N0 + 2 * N1 + N3;
    for (long i = (long)blockIdx.x * blockDim.x + threadIdx.x; i < TOT;
         i += (long)gridDim.x * blockDim.x) {
        float v; long dst; __nv_bfloat16 *ph, *pl;
        if (i < N0) {
            long l = i / (K0 * 512), r = i % (K0 * 512);
            int k = (int)(r / 512), n = (int)(r % 512);
            v = (k < DINR) ? W0[(l * DINR + k) * 512 + n] : 0.0f;
            dst = i; ph = g_w0h; pl = g_w0l;
        } else if (i < N0 + N1) {
            long e = i - N0;
            v = W1[e]; dst = e; ph = g_w1h; pl = g_w1l;
        } else if (i < N0 + 2 * N1) {
            long e = i - N0 - N1;
            v = W2[e]; dst = e; ph = g_w2h; pl = g_w2l;
        } else {
            long e = i - N0 - 2 * N1;
            long l = e / (512L * DOUTP), r = e % (512L * DOUTP);
            int k = (int)(r / DOUTP), n = (int)(r % DOUTP);
            v = (n < DOUT) ? W3[(l * 512 + k) * DOUT + n] : 0.0f;
            dst = e; ph = g_w3h; pl = g_w3l;
        }
        __nv_bfloat16 hi = __float2bfloat16(v);
        __nv_bfloat16 lo = __float2bfloat16(v - __bfloat162float(hi));
        ph[dst] = hi; pl[dst] = lo;
    }
}

__global__ void init_state(const float* __restrict__ z) {
    int m = blockIdx.x * blockDim.x + threadIdx.x;
    if (m >= MTOT) return;
    g_ld[m] = 0.0f;
#pragma unroll
    for (int j = 0; j < 12; j++) g_x[m * 12 + j] = z[m * 12 + j];
}

// writes [x1 | c | 0pad] hi/lo row-major into g_a0 for row m, given x vals
__device__ __forceinline__ void write_a0(int m, const float* xv, const float* __restrict__ c) {
    uint32_t* oh = (uint32_t*)&g_a0h[m * K0];
    uint32_t* ol = (uint32_t*)&g_a0l[m * K0];
#pragma unroll
    for (int q = 0; q < 32; q++) {
        __nv_bfloat16 h2[2], l2[2];
#pragma unroll
        for (int t = 0; t < 2; t++) {
            int k = q * 2 + t;
            float v = (k < D_HALF) ? xv[k]
                      : (k < DINR ? c[(size_t)m * 16 + (k - D_HALF)] : 0.0f);
            h2[t] = __float2bfloat16(v);
            l2[t] = __float2bfloat16(v - __bfloat162float(h2[t]));
        }
        oh[q] = pkbf(h2[0], h2[1]);
        ol[q] = pkbf(l2[0], l2[1]);
    }
}

__global__ void concat_kernel(const float* __restrict__ c) {
    int m = blockIdx.x * blockDim.x + threadIdx.x;
    if (m >= MTOT) return;
    float xv[D_HALF];
#pragma unroll
    for (int j = 0; j < D_HALF; j++) xv[j] = g_x[m * 12 + j];
    write_a0(m, xv, c);
}

// ---------------- GEMM via mma.sync bf16x3, double-buffered, 2D grid ----------------
// blockIdx.x = m tile, blockIdx.y = n chunk.
template<int NCN, int NTN, int KTOT, int LDA, int MODE>
__global__ void __launch_bounds__(256) gemm_mma(int asel, int osel, int wsel, int layer,
                                                const float* __restrict__ bias, int bias_n)
{
    extern __shared__ char smem[];
    constexpr int SA_STR = 72;                     // 144B rows, ldmatrix conflict-free
    constexpr int SW_STR = NCN + 8;
    constexpr int A_BYTES = 128 * SA_STR * 2;      // 18432
    constexpr int W_BYTES = 64 * SW_STR * 2;
    constexpr int SM_AH = 0;
    constexpr int SM_AL = A_BYTES;
    constexpr int SM_WH = 2 * A_BYTES;
    constexpr int SM_WL = 2 * A_BYTES + W_BYTES;
    constexpr int BUF = 2 * A_BYTES + 2 * W_BYTES;
    constexpr int NTILE = NCN / 8;
    constexpr int WSEG = NCN / 8;
    constexpr int NK = KTOT / 64;

    const int tid = threadIdx.x, wid = tid >> 5, lane = tid & 31;
    const int tile = blockIdx.x;
    const int nc = blockIdx.y;
    uint32_t sb = smem_u32(smem);

    const __nv_bfloat16* Ah = (asel == 0) ? g_a0h : (asel == 1 ? g_bAh : g_bBh);
    const __nv_bfloat16* Al = (asel == 0) ? g_a0l : (asel == 1 ? g_bAl : g_bBl);
    const __nv_bfloat16 *Wh, *Wl;
    if      (wsel == 0) { Wh = g_w0h + (size_t)layer * K0 * 512;    Wl = g_w0l + (size_t)layer * K0 * 512; }
    else if (wsel == 1) { Wh = g_w1h + (size_t)layer * 512 * 512;   Wl = g_w1l + (size_t)layer * 512 * 512; }
    else if (wsel == 2) { Wh = g_w2h + (size_t)layer * 512 * 512;   Wl = g_w2l + (size_t)layer * 512 * 512; }
    else                { Wh = g_w3h + (size_t)layer * 512 * DOUTP; Wl = g_w3l + (size_t)layer * 512 * DOUTP; }

    const char* agh = (const char*)(Ah + (size_t)tile * MT * LDA);
    const char* agl = (const char*)(Al + (size_t)tile * MT * LDA);
    const char* wgh = (const char*)(Wh + (size_t)nc * NCN);
    const char* wgl = (const char*)(Wl + (size_t)nc * NCN);

    const uint32_t a_off = (uint32_t)((wid * 16 + (lane & 15)) * SA_STR * 2 + (lane >> 4) * 16);
    const uint32_t b_off = (uint32_t)((lane & 15) * SW_STR * 2 + (lane >> 4) * 16);

    // stage chunk kc into buffer b
    auto stage = [&](int kc, int b) {
        uint32_t base = sb + (uint32_t)(b * BUF);
        for (int i = tid; i < 1024; i += 256) {
            int r = i >> 3, seg = i & 7;
            uint32_t so = (uint32_t)(r * SA_STR * 2 + seg * 16);
            size_t go = (size_t)r * LDA * 2 + (size_t)kc * 128 + seg * 16;
            cp16(base + SM_AH + so, agh + go);
            cp16(base + SM_AL + so, agl + go);
        }
        for (int i = tid; i < 64 * WSEG; i += 256) {
            int r = i / WSEG, seg = i % WSEG;
            uint32_t so = (uint32_t)(r * SW_STR * 2 + seg * 16);
            size_t go = ((size_t)kc * 64 + r) * NTN * 2 + seg * 16;
            cp16(base + SM_WH + so, wgh + go);
            cp16(base + SM_WL + so, wgl + go);
        }
        asm volatile("cp.async.commit_group;" ::: "memory");
    };

    float acc[NTILE][4];
#pragma unroll
    for (int t = 0; t < NTILE; t++)
#pragma unroll
        for (int q = 0; q < 4; q++) acc[t][q] = 0.0f;

    stage(0, 0);
    for (int kc = 0; kc < NK; kc++) {
        if (kc + 1 < NK) {
            stage(kc + 1, (kc + 1) & 1);
            asm volatile("cp.async.wait_group 1;" ::: "memory");
        } else {
            asm volatile("cp.async.wait_group 0;" ::: "memory");
        }
        __syncthreads();

        uint32_t base = sb + (uint32_t)((kc & 1) * BUF);
#pragma unroll
        for (int s = 0; s < 4; s++) {
            uint32_t ahr[4], alr[4];
            ldsm4(ahr, base + SM_AH + a_off + s * 32);
            ldsm4(alr, base + SM_AL + a_off + s * 32);
            uint32_t brow = b_off + (uint32_t)(s * 16 * SW_STR * 2);
#pragma unroll
            for (int jb = 0; jb < NTILE / 2; jb++) {
                uint32_t bh[4], bl[4];
                ldsm4t(bh, base + SM_WH + brow + jb * 32);
                ldsm4t(bl, base + SM_WL + brow + jb * 32);
                mma_bf16(acc[2 * jb],     ahr, bh[0], bh[1]);
                mma_bf16(acc[2 * jb],     ahr, bl[0], bl[1]);
                mma_bf16(acc[2 * jb],     alr, bh[0], bh[1]);
                mma_bf16(acc[2 * jb + 1], ahr, bh[2], bh[3]);
                mma_bf16(acc[2 * jb + 1], ahr, bl[2], bl[3]);
                mma_bf16(acc[2 * jb + 1], alr, bh[2], bh[3]);
            }
        }
        __syncthreads();   // compute done before next stage overwrites this buffer
    }

    // ---- epilogue ----
    const int r0 = tile * MT + wid * 16 + (lane >> 2);
    const int cbase = nc * NCN + (lane & 3) * 2;
    if (MODE == 0) {
        __nv_bfloat16* Oh = (osel == 1) ? g_bAh : g_bBh;
        __nv_bfloat16* Ol = (osel == 1) ? g_bAl : g_bBl;
#pragma unroll
        for (int t = 0; t < NTILE; t++) {
            int col = cbase + t * 8;
            float b0 = __ldg(&bias[col]), b1 = __ldg(&bias[col + 1]);
#pragma unroll
            for (int h = 0; h < 2; h++) {
                int row = r0 + h * 8;
                float v0 = eluf(acc[t][2 * h] + b0);
                float v1 = eluf(acc[t][2 * h + 1] + b1);
                __nv_bfloat16 h0 = __float2bfloat16(v0);
                __nv_bfloat16 h1 = __float2bfloat16(v1);
                __nv_bfloat16 l0 = __float2bfloat16(v0 - __bfloat162float(h0));
                __nv_bfloat16 l1 = __float2bfloat16(v1 - __bfloat162float(h1));
                *(uint32_t*)&Oh[(size_t)row * HID + col] = pkbf(h0, h1);
                *(uint32_t*)&Ol[(size_t)row * HID + col] = pkbf(l0, l1);
            }
        }
    } else {
#pragma unroll
        for (int t = 0; t < NTILE; t++) {
            int col = cbase + t * 8;
            float b0 = (col < bias_n) ? __ldg(&bias[col]) : 0.0f;
            float b1 = (col + 1 < bias_n) ? __ldg(&bias[col + 1]) : 0.0f;
#pragma unroll
            for (int h = 0; h < 2; h++) {
                int row = r0 + h * 8;
                g_params[(size_t)row * DOUTP + col]     = acc[t][2 * h] + b0;
                g_params[(size_t)row * DOUTP + col + 1] = acc[t][2 * h + 1] + b1;
            }
        }
    }
}

// ---------------- spline + permutation + next-layer concat ----------------
__global__ void spline_kernel(const int* __restrict__ perms, int layer,
                              const float* __restrict__ c) {
    int m = blockIdx.x * blockDim.x + threadIdx.x;
    if (m >= MTOT) return;
    const float* pall = &g_params[(size_t)m * DOUTP];
    float cat[12];
#pragma unroll
    for (int j = 0; j < D_HALF; j++) cat[j] = g_x[m * 12 + j];
    float ldsum = 0.0f;
#pragma unroll
    for (int d = 0; d < D_HALF; d++) {
        const float* p = pall + d * SPP;
        float e[KBINS];
        float mx = p[0];
#pragma unroll
        for (int i = 1; i < KBINS; i++) mx = fmaxf(mx, p[i]);
        float s = 0.0f;
#pragma unroll
        for (int i = 0; i < KBINS; i++) { e[i] = expf(p[i] - mx); s += e[i]; }
        float inv = 1.0f / s;
        float cw[KBINS + 1];
        cw[0] = -BVAL;
        {
            float run = 0.0f;
#pragma unroll
            for (int i = 0; i < KBINS - 1; i++) {
                run += 0.001f + 0.992f * e[i] * inv;
                cw[i + 1] = 2.0f * BVAL * run - BVAL;
            }
        }
        cw[KBINS] = BVAL;
        mx = p[KBINS];
#pragma unroll
        for (int i = 1; i < KBINS; i++) mx = fmaxf(mx, p[KBINS + i]);
        s = 0.0f;
#pragma unroll
        for (int i = 0; i < KBINS; i++) { e[i] = expf(p[KBINS + i] - mx); s += e[i]; }
        inv = 1.0f / s;
        float chn[KBINS + 1];
        chn[0] = -BVAL;
        {
            float run = 0.0f;
#pragma unroll
            for (int i = 0; i < KBINS - 1; i++) {
                run += 0.001f + 0.992f * e[i] * inv;
                chn[i + 1] = 2.0f * BVAL * run - BVAL;
            }
        }
        chn[KBINS] = BVAL;
        float dv[KBINS + 1];
        dv[0] = 1.0f; dv[KBINS] = 1.0f;
#pragma unroll
        for (int i = 1; i < KBINS; i++) dv[i] = 0.001f + softplusf(p[2 * KBINS + i - 1]);

        float x = g_x[m * 12 + D_HALF + d];
        float xc = fminf(fmaxf(x, -BVAL), BVAL);
        int idx = 0;
#pragma unroll
        for (int i = 1; i < KBINS; i++) idx += (xc >= cw[i]) ? 1 : 0;
        float icw = cw[idx], iw = cw[idx + 1] - cw[idx];
        float ich = chn[idx], ih = chn[idx + 1] - chn[idx];
        float delta = ih / iw;
        float d0 = dv[idx], d1 = dv[idx + 1];
        float th = (xc - icw) / iw;
        float t1m = th * (1.0f - th);
        float num = ih * (delta * th * th + d0 * t1m);
        float den = delta + (d0 + d1 - 2.0f * delta) * t1m;
        float o = ich + num / den;
        float omt = 1.0f - th;
        float dnum = delta * delta * (d1 * th * th + 2.0f * delta * t1m + d0 * omt * omt);
        float lad = logf(dnum) - 2.0f * logf(den);
        bool inside = (x >= -BVAL) && (x <= BVAL);
        cat[D_HALF + d] = inside ? o : x;
        ldsum += inside ? lad : 0.0f;
    }
    g_ld[m] += ldsum;
    float xn[12];
    if (layer < LAYERS - 1) {
#pragma unroll
        for (int j = 0; j < 12; j++) xn[j] = cat[perms[layer * 12 + j]];
#pragma unroll
        for (int j = 0; j < 12; j++) g_x[m * 12 + j] = xn[j];
        write_a0(m, xn, c);   // fused concat for next layer
    } else {
#pragma unroll
        for (int j = 0; j < 12; j++) g_x[m * 12 + j] = cat[j];
    }
}

__global__ void final_kernel(float* __restrict__ out) {
    int m = blockIdx.x * blockDim.x + threadIdx.x;
    if (m >= MTOT) return;
#pragma unroll
    for (int j = 0; j < 12; j++) out[m * 12 + j] = g_x[m * 12 + j];
    out[(size_t)MTOT * 12 + m] = g_ld[m];
}

// ---------------- host ----------------
extern "C" void kernel_launch(void* const* d_in, const int* in_sizes, int n_in,
                              void* d_out, int out_size)
{
    const float* z  = (const float*)d_in[0];
    const float* c  = (const float*)d_in[1];
    const float* W0 = (const float*)d_in[2];
    const float* b0 = (const float*)d_in[3];
    const float* W1 = (const float*)d_in[4];
    const float* b1 = (const float*)d_in[5];
    const float* W2 = (const float*)d_in[6];
    const float* b2 = (const float*)d_in[7];
    const float* W3 = (const float*)d_in[8];
    const float* b3 = (const float*)d_in[9];
    const int* perms = (const int*)d_in[10];

    const int SM_G12 = 2 * (2 * (128 * 72 * 2) + 2 * (64 * 136 * 2));  // 143360
    const int SM_G3  = 2 * (2 * (128 * 72 * 2) + 2 * (64 * 168 * 2));  // 159744
    cudaFuncSetAttribute(gemm_mma<128, 512,  64,  64, 0>, cudaFuncAttributeMaxDynamicSharedMemorySize, SM_G12);
    cudaFuncSetAttribute(gemm_mma<128, 512, 512, 512, 0>, cudaFuncAttributeMaxDynamicSharedMemorySize, SM_G12);
    cudaFuncSetAttribute(gemm_mma<160, 160, 512, 512, 1>, cudaFuncAttributeMaxDynamicSharedMemorySize, SM_G3);

    prep_weights<<<2048, 256>>>(W0, W1, W2, W3);
    init_state<<<MTOT / 256, 256>>>(z);
    concat_kernel<<<MTOT / 256, 256>>>(c);
    dim3 g12(MTILES, 4), g3(MTILES, 1);
    for (int l = 0; l < LAYERS; l++) {
        gemm_mma<128, 512,  64,  64, 0><<<g12, 256, SM_G12>>>(0, 1, 0, l, b0 + l * 512, 512);
        gemm_mma<128, 512, 512, 512, 0><<<g12, 256, SM_G12>>>(1, 2, 1, l, b1 + l * 512, 512);
        gemm_mma<128, 512, 512, 512, 0><<<g12, 256, SM_G12>>>(2, 1, 2, l, b2 + l * 512, 512);
        gemm_mma<160, 160, 512, 512, 1><<<g3, 256, SM_G3>>>(1, 0, 3, l, b3 + l * DOUT, DOUT);
        spline_kernel<<<MTOT / 256, 256>>>(perms, l, c);
    }
    final_kernel<<<MTOT / 256, 256>>>((float*)d_out);
}

// round 9
// speedup vs baseline: 2.4442x; 1.1505x over previous
#include <cuda_runtime.h>
#include <cuda_bf16.h>
#include <math.h>
#include <stdint.h>

#define LAYERS  8
#define MTOT    32768
#define MT      128
#define MTILES  (MTOT / MT)      // 256
#define HID     512
#define DINR    22
#define K0      64               // padded K for GEMM0
#define DOUT    138
#define DOUTP   160              // padded N for GEMM3
#define KBINS   8
#define BVAL    3.0f
#define D_HALF  6
#define SPP     23

// ---------------- device global scratch ----------------
__device__ __nv_bfloat16 g_w0h[LAYERS * K0 * 512];
__device__ __nv_bfloat16 g_w0l[LAYERS * K0 * 512];
__device__ __nv_bfloat16 g_w1h[LAYERS * 512 * 512];
__device__ __nv_bfloat16 g_w1l[LAYERS * 512 * 512];
__device__ __nv_bfloat16 g_w2h[LAYERS * 512 * 512];
__device__ __nv_bfloat16 g_w2l[LAYERS * 512 * 512];
__device__ __nv_bfloat16 g_w3h[LAYERS * 512 * DOUTP];
__device__ __nv_bfloat16 g_w3l[LAYERS * 512 * DOUTP];
__device__ __nv_bfloat16 g_a0h[MTOT * K0];
__device__ __nv_bfloat16 g_a0l[MTOT * K0];
__device__ __nv_bfloat16 g_bAh[MTOT * HID];
__device__ __nv_bfloat16 g_bAl[MTOT * HID];
__device__ __nv_bfloat16 g_bBh[MTOT * HID];
__device__ __nv_bfloat16 g_bBl[MTOT * HID];
__device__ float g_params[(size_t)MTOT * DOUTP];
__device__ float g_x[MTOT * 12];
__device__ float g_ld[MTOT];

// ---------------- helpers ----------------
__device__ __forceinline__ float eluf(float v) { return v > 0.0f ? v : expm1f(v); }
__device__ __forceinline__ float softplusf(float v) { return v > 20.0f ? v : log1pf(expf(v)); }

__device__ __forceinline__ uint32_t smem_u32(const void* p) {
    uint32_t a;
    asm("{ .reg .u64 t; cvta.to.shared.u64 t, %1; cvt.u32.u64 %0, t; }" : "=r"(a) : "l"(p));
    return a;
}
__device__ __forceinline__ uint32_t pkbf(__nv_bfloat16 a, __nv_bfloat16 b) {
    return (uint32_t)__bfloat16_as_ushort(a) | ((uint32_t)__bfloat16_as_ushort(b) << 16);
}
__device__ __forceinline__ void cp16(uint32_t sdst, const void* gsrc) {
    asm volatile("cp.async.cg.shared.global [%0], [%1], 16;" :: "r"(sdst), "l"(gsrc));
}
__device__ __forceinline__ void ldsm4(uint32_t* r, uint32_t a) {
    asm volatile("ldmatrix.sync.aligned.m8n8.x4.shared.b16 {%0,%1,%2,%3}, [%4];"
                 : "=r"(r[0]), "=r"(r[1]), "=r"(r[2]), "=r"(r[3]) : "r"(a));
}
__device__ __forceinline__ void ldsm4t(uint32_t* r, uint32_t a) {
    asm volatile("ldmatrix.sync.aligned.m8n8.x4.trans.shared.b16 {%0,%1,%2,%3}, [%4];"
                 : "=r"(r[0]), "=r"(r[1]), "=r"(r[2]), "=r"(r[3]) : "r"(a));
}
__device__ __forceinline__ void mma_bf16(float* d, const uint32_t* a, uint32_t b0, uint32_t b1) {
    asm volatile(
        "mma.sync.aligned.m16n8k16.row.col.f32.bf16.bf16.f32 "
        "{%0,%1,%2,%3}, {%4,%5,%6,%7}, {%8,%9}, {%0,%1,%2,%3};"
        : "+f"(d[0]), "+f"(d[1]), "+f"(d[2]), "+f"(d[3])
        : "r"(a[0]), "r"(a[1]), "r"(a[2]), "r"(a[3]), "r"(b0), "r"(b1));
}

// ---------------- prep: weights -> bf16 hi/lo k-major blobs ----------------
__global__ void prep_weights(const float* __restrict__ W0, const float* __restrict__ W1,
                             const float* __restrict__ W2, const float* __restrict__ W3) {
    const long N0 = (long)LAYERS * K0 * 512;
    const long N1 = (long)LAYERS * 512 * 512;
    const long N3 = (long)LAYERS * 512 * DOUTP;
    const long TOT = N0 + 2 * N1 + N3;
    for (long i = (long)blockIdx.x * blockDim.x + threadIdx.x; i < TOT;
         i += (long)gridDim.x * blockDim.x) {
        float v; long dst; __nv_bfloat16 *ph, *pl;
        if (i < N0) {
            long l = i / (K0 * 512), r = i % (K0 * 512);
            int k = (int)(r / 512), n = (int)(r % 512);
            v = (k < DINR) ? W0[(l * DINR + k) * 512 + n] : 0.0f;
            dst = i; ph = g_w0h; pl = g_w0l;
        } else if (i < N0 + N1) {
            long e = i - N0;
            v = W1[e]; dst = e; ph = g_w1h; pl = g_w1l;
        } else if (i < N0 + 2 * N1) {
            long e = i - N0 - N1;
            v = W2[e]; dst = e; ph = g_w2h; pl = g_w2l;
        } else {
            long e = i - N0 - 2 * N1;
            long l = e / (512L * DOUTP), r = e % (512L * DOUTP);
            int k = (int)(r / DOUTP), n = (int)(r % DOUTP);
            v = (n < DOUT) ? W3[(l * 512 + k) * DOUT + n] : 0.0f;
            dst = e; ph = g_w3h; pl = g_w3l;
        }
        __nv_bfloat16 hi = __float2bfloat16(v);
        __nv_bfloat16 lo = __float2bfloat16(v - __bfloat162float(hi));
        ph[dst] = hi; pl[dst] = lo;
    }
}

__global__ void init_state(const float* __restrict__ z) {
    int m = blockIdx.x * blockDim.x + threadIdx.x;
    if (m >= MTOT) return;
    g_ld[m] = 0.0f;
#pragma unroll
    for (int j = 0; j < 12; j++) g_x[m * 12 + j] = z[m * 12 + j];
}

// writes [x1 | c | 0pad] hi/lo row-major into g_a0 for row m, given x vals
__device__ __forceinline__ void write_a0(int m, const float* xv, const float* __restrict__ c) {
    uint32_t* oh = (uint32_t*)&g_a0h[m * K0];
    uint32_t* ol = (uint32_t*)&g_a0l[m * K0];
#pragma unroll
    for (int q = 0; q < 32; q++) {
        __nv_bfloat16 h2[2], l2[2];
#pragma unroll
        for (int t = 0; t < 2; t++) {
            int k = q * 2 + t;
            float v = (k < D_HALF) ? xv[k]
                      : (k < DINR ? c[(size_t)m * 16 + (k - D_HALF)] : 0.0f);
            h2[t] = __float2bfloat16(v);
            l2[t] = __float2bfloat16(v - __bfloat162float(h2[t]));
        }
        oh[q] = pkbf(h2[0], h2[1]);
        ol[q] = pkbf(l2[0], l2[1]);
    }
}

__global__ void concat_kernel(const float* __restrict__ c) {
    int m = blockIdx.x * blockDim.x + threadIdx.x;
    if (m >= MTOT) return;
    float xv[D_HALF];
#pragma unroll
    for (int j = 0; j < D_HALF; j++) xv[j] = g_x[m * 12 + j];
    write_a0(m, xv, c);
}

// ---------------- GEMM via mma.sync bf16x3, KC=32, 3-stage pipeline ----------------
// blockIdx.x = m tile, blockIdx.y = n chunk.
template<int NCN, int NTN, int KTOT, int LDA, int MODE>
__global__ void __launch_bounds__(256) gemm_mma(int asel, int osel, int wsel, int layer,
                                                const float* __restrict__ bias, int bias_n)
{
    extern __shared__ char smem[];
    constexpr int KC = 32;
    constexpr int SA_STR = 40;                     // 80B rows, phase-conflict-free
    constexpr int SW_STR = NCN + 8;                // 272B / 336B
    constexpr int A_BYTES = 128 * SA_STR * 2;      // 10240
    constexpr int W_BYTES = KC * SW_STR * 2;
    constexpr int SM_AH = 0;
    constexpr int SM_AL = A_BYTES;
    constexpr int SM_WH = 2 * A_BYTES;
    constexpr int SM_WL = 2 * A_BYTES + W_BYTES;
    constexpr int BUF = 2 * A_BYTES + 2 * W_BYTES;
    constexpr int NTILE = NCN / 8;
    constexpr int WSEG = NCN / 8;
    constexpr int NK = KTOT / KC;

    const int tid = threadIdx.x, wid = tid >> 5, lane = tid & 31;
    const int tile = blockIdx.x;
    const int nc = blockIdx.y;
    uint32_t sb = smem_u32(smem);

    const __nv_bfloat16* Ah = (asel == 0) ? g_a0h : (asel == 1 ? g_bAh : g_bBh);
    const __nv_bfloat16* Al = (asel == 0) ? g_a0l : (asel == 1 ? g_bAl : g_bBl);
    const __nv_bfloat16 *Wh, *Wl;
    if      (wsel == 0) { Wh = g_w0h + (size_t)layer * K0 * 512;    Wl = g_w0l + (size_t)layer * K0 * 512; }
    else if (wsel == 1) { Wh = g_w1h + (size_t)layer * 512 * 512;   Wl = g_w1l + (size_t)layer * 512 * 512; }
    else if (wsel == 2) { Wh = g_w2h + (size_t)layer * 512 * 512;   Wl = g_w2l + (size_t)layer * 512 * 512; }
    else                { Wh = g_w3h + (size_t)layer * 512 * DOUTP; Wl = g_w3l + (size_t)layer * 512 * DOUTP; }

    const char* agh = (const char*)(Ah + (size_t)tile * MT * LDA);
    const char* agl = (const char*)(Al + (size_t)tile * MT * LDA);
    const char* wgh = (const char*)(Wh + (size_t)nc * NCN);
    const char* wgl = (const char*)(Wl + (size_t)nc * NCN);

    const uint32_t a_off = (uint32_t)((wid * 16 + (lane & 15)) * SA_STR * 2 + (lane >> 4) * 16);
    const uint32_t b_off = (uint32_t)((lane & 15) * SW_STR * 2 + (lane >> 4) * 16);

    // stage chunk kc into buffer b
    auto stage = [&](int kc, int b) {
        uint32_t base = sb + (uint32_t)(b * BUF);
        // A: 128 rows x 4 segs of 16B (KC=32 -> 64B per row)
        for (int i = tid; i < 512; i += 256) {
            int r = i >> 2, seg = i & 3;
            uint32_t so = (uint32_t)(r * SA_STR * 2 + seg * 16);
            size_t go = (size_t)r * LDA * 2 + (size_t)kc * 64 + seg * 16;
            cp16(base + SM_AH + so, agh + go);
            cp16(base + SM_AL + so, agl + go);
        }
        // W: KC rows x WSEG segs
        for (int i = tid; i < KC * WSEG; i += 256) {
            int r = i / WSEG, seg = i % WSEG;
            uint32_t so = (uint32_t)(r * SW_STR * 2 + seg * 16);
            size_t go = ((size_t)kc * KC + r) * NTN * 2 + seg * 16;
            cp16(base + SM_WH + so, wgh + go);
            cp16(base + SM_WL + so, wgl + go);
        }
        asm volatile("cp.async.commit_group;" ::: "memory");
    };

    float acc[NTILE][4];
#pragma unroll
    for (int t = 0; t < NTILE; t++)
#pragma unroll
        for (int q = 0; q < 4; q++) acc[t][q] = 0.0f;

    stage(0, 0);
    if (NK > 1) stage(1, 1);

    for (int kc = 0; kc < NK; kc++) {
        if (kc + 2 < NK) {
            stage(kc + 2, (kc + 2) % 3);
            asm volatile("cp.async.wait_group 2;" ::: "memory");
        } else if (kc + 2 == NK) {
            asm volatile("cp.async.wait_group 1;" ::: "memory");
        } else {
            asm volatile("cp.async.wait_group 0;" ::: "memory");
        }
        __syncthreads();

        uint32_t base = sb + (uint32_t)((kc % 3) * BUF);
#pragma unroll
        for (int s = 0; s < KC / 16; s++) {
            uint32_t ahr[4], alr[4];
            ldsm4(ahr, base + SM_AH + a_off + s * 32);
            ldsm4(alr, base + SM_AL + a_off + s * 32);
            uint32_t brow = b_off + (uint32_t)(s * 16 * SW_STR * 2);
#pragma unroll
            for (int jb = 0; jb < NTILE / 2; jb++) {
                uint32_t bh[4], bl[4];
                ldsm4t(bh, base + SM_WH + brow + jb * 32);
                ldsm4t(bl, base + SM_WL + brow + jb * 32);
                mma_bf16(acc[2 * jb],     ahr, bh[0], bh[1]);
                mma_bf16(acc[2 * jb],     ahr, bl[0], bl[1]);
                mma_bf16(acc[2 * jb],     alr, bh[0], bh[1]);
                mma_bf16(acc[2 * jb + 1], ahr, bh[2], bh[3]);
                mma_bf16(acc[2 * jb + 1], ahr, bl[2], bl[3]);
                mma_bf16(acc[2 * jb + 1], alr, bh[2], bh[3]);
            }
        }
        __syncthreads();   // compute done before this buffer is restaged
    }

    // ---- epilogue ----
    const int r0 = tile * MT + wid * 16 + (lane >> 2);
    const int cbase = nc * NCN + (lane & 3) * 2;
    if (MODE == 0) {
        __nv_bfloat16* Oh = (osel == 1) ? g_bAh : g_bBh;
        __nv_bfloat16* Ol = (osel == 1) ? g_bAl : g_bBl;
#pragma unroll
        for (int t = 0; t < NTILE; t++) {
            int col = cbase + t * 8;
            float b0 = __ldg(&bias[col]), b1 = __ldg(&bias[col + 1]);
#pragma unroll
            for (int h = 0; h < 2; h++) {
                int row = r0 + h * 8;
                float v0 = eluf(acc[t][2 * h] + b0);
                float v1 = eluf(acc[t][2 * h + 1] + b1);
                __nv_bfloat16 h0 = __float2bfloat16(v0);
                __nv_bfloat16 h1 = __float2bfloat16(v1);
                __nv_bfloat16 l0 = __float2bfloat16(v0 - __bfloat162float(h0));
                __nv_bfloat16 l1 = __float2bfloat16(v1 - __bfloat162float(h1));
                *(uint32_t*)&Oh[(size_t)row * HID + col] = pkbf(h0, h1);
                *(uint32_t*)&Ol[(size_t)row * HID + col] = pkbf(l0, l1);
            }
        }
    } else {
#pragma unroll
        for (int t = 0; t < NTILE; t++) {
            int col = cbase + t * 8;
            float b0 = (col < bias_n) ? __ldg(&bias[col]) : 0.0f;
            float b1 = (col + 1 < bias_n) ? __ldg(&bias[col + 1]) : 0.0f;
#pragma unroll
            for (int h = 0; h < 2; h++) {
                int row = r0 + h * 8;
                g_params[(size_t)row * DOUTP + col]     = acc[t][2 * h] + b0;
                g_params[(size_t)row * DOUTP + col + 1] = acc[t][2 * h + 1] + b1;
            }
        }
    }
}

// ---------------- spline + permutation + next-layer concat ----------------
__global__ void spline_kernel(const int* __restrict__ perms, int layer,
                              const float* __restrict__ c) {
    int m = blockIdx.x * blockDim.x + threadIdx.x;
    if (m >= MTOT) return;
    const float* pall = &g_params[(size_t)m * DOUTP];
    float cat[12];
#pragma unroll
    for (int j = 0; j < D_HALF; j++) cat[j] = g_x[m * 12 + j];
    float ldsum = 0.0f;
#pragma unroll
    for (int d = 0; d < D_HALF; d++) {
        const float* p = pall + d * SPP;
        float e[KBINS];
        float mx = p[0];
#pragma unroll
        for (int i = 1; i < KBINS; i++) mx = fmaxf(mx, p[i]);
        float s = 0.0f;
#pragma unroll
        for (int i = 0; i < KBINS; i++) { e[i] = expf(p[i] - mx); s += e[i]; }
        float inv = 1.0f / s;
        float cw[KBINS + 1];
        cw[0] = -BVAL;
        {
            float run = 0.0f;
#pragma unroll
            for (int i = 0; i < KBINS - 1; i++) {
                run += 0.001f + 0.992f * e[i] * inv;
                cw[i + 1] = 2.0f * BVAL * run - BVAL;
            }
        }
        cw[KBINS] = BVAL;
        mx = p[KBINS];
#pragma unroll
        for (int i = 1; i < KBINS; i++) mx = fmaxf(mx, p[KBINS + i]);
        s = 0.0f;
#pragma unroll
        for (int i = 0; i < KBINS; i++) { e[i] = expf(p[KBINS + i] - mx); s += e[i]; }
        inv = 1.0f / s;
        float chn[KBINS + 1];
        chn[0] = -BVAL;
        {
            float run = 0.0f;
#pragma unroll
            for (int i = 0; i < KBINS - 1; i++) {
                run += 0.001f + 0.992f * e[i] * inv;
                chn[i + 1] = 2.0f * BVAL * run - BVAL;
            }
        }
        chn[KBINS] = BVAL;
        float dv[KBINS + 1];
        dv[0] = 1.0f; dv[KBINS] = 1.0f;
#pragma unroll
        for (int i = 1; i < KBINS; i++) dv[i] = 0.001f + softplusf(p[2 * KBINS + i - 1]);

        float x = g_x[m * 12 + D_HALF + d];
        float xc = fminf(fmaxf(x, -BVAL), BVAL);
        int idx = 0;
#pragma unroll
        for (int i = 1; i < KBINS; i++) idx += (xc >= cw[i]) ? 1 : 0;
        float icw = cw[idx], iw = cw[idx + 1] - cw[idx];
        float ich = chn[idx], ih = chn[idx + 1] - chn[idx];
        float delta = ih / iw;
        float d0 = dv[idx], d1 = dv[idx + 1];
        float th = (xc - icw) / iw;
        float t1m = th * (1.0f - th);
        float num = ih * (delta * th * th + d0 * t1m);
        float den = delta + (d0 + d1 - 2.0f * delta) * t1m;
        float o = ich + num / den;
        float omt = 1.0f - th;
        float dnum = delta * delta * (d1 * th * th + 2.0f * delta * t1m + d0 * omt * omt);
        float lad = logf(dnum) - 2.0f * logf(den);
        bool inside = (x >= -BVAL) && (x <= BVAL);
        cat[D_HALF + d] = inside ? o : x;
        ldsum += inside ? lad : 0.0f;
    }
    g_ld[m] += ldsum;
    float xn[12];
    if (layer < LAYERS - 1) {
#pragma unroll
        for (int j = 0; j < 12; j++) xn[j] = cat[perms[layer * 12 + j]];
#pragma unroll
        for (int j = 0; j < 12; j++) g_x[m * 12 + j] = xn[j];
        write_a0(m, xn, c);   // fused concat for next layer
    } else {
#pragma unroll
        for (int j = 0; j < 12; j++) g_x[m * 12 + j] = cat[j];
    }
}

__global__ void final_kernel(float* __restrict__ out) {
    int m = blockIdx.x * blockDim.x + threadIdx.x;
    if (m >= MTOT) return;
#pragma unroll
    for (int j = 0; j < 12; j++) out[m * 12 + j] = g_x[m * 12 + j];
    out[(size_t)MTOT * 12 + m] = g_ld[m];
}

// ---------------- host ----------------
extern "C" void kernel_launch(void* const* d_in, const int* in_sizes, int n_in,
                              void* d_out, int out_size)
{
    const float* z  = (const float*)d_in[0];
    const float* c  = (const float*)d_in[1];
    const float* W0 = (const float*)d_in[2];
    const float* b0 = (const float*)d_in[3];
    const float* W1 = (const float*)d_in[4];
    const float* b1 = (const float*)d_in[5];
    const float* W2 = (const float*)d_in[6];
    const float* b2 = (const float*)d_in[7];
    const float* W3 = (const float*)d_in[8];
    const float* b3 = (const float*)d_in[9];
    const int* perms = (const int*)d_in[10];

    // per-buffer: 2*(128*40*2) + 2*(32*(NCN+8)*2); 3 buffers
    const int SM_G12 = 3 * (2 * (128 * 40 * 2) + 2 * (32 * 136 * 2));  // 113,664
    const int SM_G3  = 3 * (2 * (128 * 40 * 2) + 2 * (32 * 168 * 2));  // 125,952
    cudaFuncSetAttribute(gemm_mma<128, 512,  64,  64, 0>, cudaFuncAttributeMaxDynamicSharedMemorySize, SM_G12);
    cudaFuncSetAttribute(gemm_mma<128, 512, 512, 512, 0>, cudaFuncAttributeMaxDynamicSharedMemorySize, SM_G12);
    cudaFuncSetAttribute(gemm_mma<160, 160, 512, 512, 1>, cudaFuncAttributeMaxDynamicSharedMemorySize, SM_G3);

    prep_weights<<<2048, 256>>>(W0, W1, W2, W3);
    init_state<<<MTOT / 256, 256>>>(z);
    concat_kernel<<<MTOT / 256, 256>>>(c);
    dim3 g12(MTILES, 4), g3(MTILES, 1);
    for (int l = 0; l < LAYERS; l++) {
        gemm_mma<128, 512,  64,  64, 0><<<g12, 256, SM_G12>>>(0, 1, 0, l, b0 + l * 512, 512);
        gemm_mma<128, 512, 512, 512, 0><<<g12, 256, SM_G12>>>(1, 2, 1, l, b1 + l * 512, 512);
        gemm_mma<128, 512, 512, 512, 0><<<g12, 256, SM_G12>>>(2, 1, 2, l, b2 + l * 512, 512);
        gemm_mma<160, 160, 512, 512, 1><<<g3, 256, SM_G3>>>(1, 0, 3, l, b3 + l * DOUT, DOUT);
        spline_kernel<<<MTOT / 256, 256>>>(perms, l, c);
    }
    final_kernel<<<MTOT / 256, 256>>>((float*)d_out);
}

// round 10
// speedup vs baseline: 2.5933x; 1.0610x over previous
#include <cuda_runtime.h>
#include <cuda_bf16.h>
#include <math.h>
#include <stdint.h>

#define LAYERS  8
#define MTOT    32768
#define MT      128
#define MTILES  (MTOT / MT)      // 256
#define HID     512
#define DINR    22
#define DOUT    138
#define DOUTP   160
#define KBINS   8
#define BVAL    3.0f
#define D_HALF  6
#define SPP     23

// ---------------- device global scratch ----------------
__device__ __nv_bfloat16 g_w1h[LAYERS * 512 * 512];
__device__ __nv_bfloat16 g_w1l[LAYERS * 512 * 512];
__device__ __nv_bfloat16 g_w2h[LAYERS * 512 * 512];
__device__ __nv_bfloat16 g_w2l[LAYERS * 512 * 512];
__device__ __nv_bfloat16 g_w3h[LAYERS * 512 * DOUTP];
__device__ __nv_bfloat16 g_w3l[LAYERS * 512 * DOUTP];
__device__ __nv_bfloat16 g_bAh[MTOT * HID];
__device__ __nv_bfloat16 g_bAl[MTOT * HID];
__device__ __nv_bfloat16 g_bBh[MTOT * HID];
__device__ __nv_bfloat16 g_bBl[MTOT * HID];
__device__ float g_params[(size_t)MTOT * DOUTP];
__device__ float g_x[MTOT * 12];
__device__ float g_ld[MTOT];

// ---------------- helpers ----------------
__device__ __forceinline__ float eluf(float v) { return v > 0.0f ? v : expm1f(v); }
__device__ __forceinline__ float softplusf(float v) { return v > 20.0f ? v : log1pf(expf(v)); }

__device__ __forceinline__ uint32_t smem_u32(const void* p) {
    uint32_t a;
    asm("{ .reg .u64 t; cvta.to.shared.u64 t, %1; cvt.u32.u64 %0, t; }" : "=r"(a) : "l"(p));
    return a;
}
__device__ __forceinline__ uint32_t pkbf(__nv_bfloat16 a, __nv_bfloat16 b) {
    return (uint32_t)__bfloat16_as_ushort(a) | ((uint32_t)__bfloat16_as_ushort(b) << 16);
}
__device__ __forceinline__ void cp16(uint32_t sdst, const void* gsrc) {
    asm volatile("cp.async.cg.shared.global [%0], [%1], 16;" :: "r"(sdst), "l"(gsrc));
}
__device__ __forceinline__ void ldsm4(uint32_t* r, uint32_t a) {
    asm volatile("ldmatrix.sync.aligned.m8n8.x4.shared.b16 {%0,%1,%2,%3}, [%4];"
                 : "=r"(r[0]), "=r"(r[1]), "=r"(r[2]), "=r"(r[3]) : "r"(a));
}
__device__ __forceinline__ void ldsm4t(uint32_t* r, uint32_t a) {
    asm volatile("ldmatrix.sync.aligned.m8n8.x4.trans.shared.b16 {%0,%1,%2,%3}, [%4];"
                 : "=r"(r[0]), "=r"(r[1]), "=r"(r[2]), "=r"(r[3]) : "r"(a));
}
__device__ __forceinline__ void mma_bf16(float* d, const uint32_t* a, uint32_t b0, uint32_t b1) {
    asm volatile(
        "mma.sync.aligned.m16n8k16.row.col.f32.bf16.bf16.f32 "
        "{%0,%1,%2,%3}, {%4,%5,%6,%7}, {%8,%9}, {%0,%1,%2,%3};"
        : "+f"(d[0]), "+f"(d[1]), "+f"(d[2]), "+f"(d[3])
        : "r"(a[0]), "r"(a[1]), "r"(a[2]), "r"(a[3]), "r"(b0), "r"(b1));
}

// ---------------- prep: W1/W2/W3 -> bf16 hi/lo k-major blobs ----------------
__global__ void prep_weights(const float* __restrict__ W1, const float* __restrict__ W2,
                             const float* __restrict__ W3) {
    const long N1 = (long)LAYERS * 512 * 512;
    const long N3 = (long)LAYERS * 512 * DOUTP;
    const long TOT = 2 * N1 + N3;
    for (long i = (long)blockIdx.x * blockDim.x + threadIdx.x; i < TOT;
         i += (long)gridDim.x * blockDim.x) {
        float v; long dst; __nv_bfloat16 *ph, *pl;
        if (i < N1) {
            v = W1[i]; dst = i; ph = g_w1h; pl = g_w1l;
        } else if (i < 2 * N1) {
            long e = i - N1;
            v = W2[e]; dst = e; ph = g_w2h; pl = g_w2l;
        } else {
            long e = i - 2 * N1;
            long l = e / (512L * DOUTP), r = e % (512L * DOUTP);
            int k = (int)(r / DOUTP), n = (int)(r % DOUTP);
            v = (n < DOUT) ? W3[(l * 512 + k) * DOUT + n] : 0.0f;
            dst = e; ph = g_w3h; pl = g_w3l;
        }
        __nv_bfloat16 hi = __float2bfloat16(v);
        __nv_bfloat16 lo = __float2bfloat16(v - __bfloat162float(hi));
        ph[dst] = hi; pl[dst] = lo;
    }
}

__global__ void init_state(const float* __restrict__ z) {
    int m = blockIdx.x * blockDim.x + threadIdx.x;
    if (m >= MTOT) return;
    g_ld[m] = 0.0f;
#pragma unroll
    for (int j = 0; j < 12; j++) g_x[m * 12 + j] = z[m * 12 + j];
}

// ---------------- GEMM0: SIMT fp32 (K=22), writes g_bA hi/lo blob ----------------
// grid 1024 x block 256; CTA = 32 rows; thread = col pair (2*tid), 32 rows.
__global__ void __launch_bounds__(256) gemm0_simt(const float* __restrict__ W0,
                                                  const float* __restrict__ b0,
                                                  const float* __restrict__ c, int layer)
{
    __shared__ float inp_t[DINR][32];
    const int tid = threadIdx.x;
    const int row0 = blockIdx.x * 32;
    for (int i = tid; i < DINR * 32; i += 256) {
        int k = i >> 5, r = i & 31;
        int m = row0 + r;
        inp_t[k][r] = (k < D_HALF) ? g_x[m * 12 + k] : c[(size_t)m * 16 + (k - D_HALF)];
    }
    __syncthreads();

    const float* W = W0 + (size_t)layer * DINR * 512;
    const int j0 = tid * 2;
    float a0[32], a1[32];
#pragma unroll
    for (int r = 0; r < 32; r++) { a0[r] = 0.0f; a1[r] = 0.0f; }
#pragma unroll
    for (int k = 0; k < DINR; k++) {
        float2 w = *(const float2*)(W + (size_t)k * 512 + j0);
#pragma unroll
        for (int r = 0; r < 32; r++) {
            float hv = inp_t[k][r];
            a0[r] = fmaf(hv, w.x, a0[r]);
            a1[r] = fmaf(hv, w.y, a1[r]);
        }
    }
    float2 bv = *(const float2*)(b0 + (size_t)layer * 512 + j0);
#pragma unroll
    for (int r = 0; r < 32; r++) {
        float v0 = eluf(a0[r] + bv.x);
        float v1 = eluf(a1[r] + bv.y);
        __nv_bfloat16 h0 = __float2bfloat16(v0);
        __nv_bfloat16 h1 = __float2bfloat16(v1);
        __nv_bfloat16 l0 = __float2bfloat16(v0 - __bfloat162float(h0));
        __nv_bfloat16 l1 = __float2bfloat16(v1 - __bfloat162float(h1));
        size_t off = (size_t)(row0 + r) * HID + j0;
        *(uint32_t*)&g_bAh[off] = pkbf(h0, h1);
        *(uint32_t*)&g_bAl[off] = pkbf(l0, l1);
    }
}

// ---------------- GEMM1/2: mma.sync bf16x3, warp tile 2x4, KC=32, 3-stage ----------------
__global__ void __launch_bounds__(256, 2) gemm_mma24(int asel, int layer_base_sel,
                                                     int layer,
                                                     const float* __restrict__ bias)
{
    extern __shared__ char smem[];
    constexpr int KC = 32;
    constexpr int NCN = 128;
    constexpr int SA_STR = 40;                 // 80B rows
    constexpr int SW_STR = NCN + 8;            // 272B rows
    constexpr int A_BYTES = 128 * SA_STR * 2;  // 10240
    constexpr int W_BYTES = KC * SW_STR * 2;   // 8704
    constexpr int SM_AH = 0;
    constexpr int SM_AL = A_BYTES;
    constexpr int SM_WH = 2 * A_BYTES;
    constexpr int SM_WL = 2 * A_BYTES + W_BYTES;
    constexpr int BUF = 2 * A_BYTES + 2 * W_BYTES;
    constexpr int NK = 512 / KC;               // 16

    const int tid = threadIdx.x, wid = tid >> 5, lane = tid & 31;
    const int tile = blockIdx.x;
    const int nc = blockIdx.y;
    uint32_t sb = smem_u32(smem);

    const __nv_bfloat16* Ah = (asel == 1) ? g_bAh : g_bBh;
    const __nv_bfloat16* Al = (asel == 1) ? g_bAl : g_bBl;
    const __nv_bfloat16* Wh = ((layer_base_sel == 1) ? g_w1h : g_w2h) + (size_t)layer * 512 * 512;
    const __nv_bfloat16* Wl = ((layer_base_sel == 1) ? g_w1l : g_w2l) + (size_t)layer * 512 * 512;

    const char* agh = (const char*)(Ah + (size_t)tile * MT * 512);
    const char* agl = (const char*)(Al + (size_t)tile * MT * 512);
    const char* wgh = (const char*)(Wh + (size_t)nc * NCN);
    const char* wgl = (const char*)(Wl + (size_t)nc * NCN);

    // warp tile: row group = wid&1 (64 rows), col group = wid>>1 (32 cols)
    const int wrow = (wid & 1) * 64;
    const int wcol = (wid >> 1) * 32;
    const uint32_t a_base = (uint32_t)((wrow + (lane & 15)) * SA_STR * 2 + (lane >> 4) * 16);
    const uint32_t b_base = (uint32_t)((lane & 15) * SW_STR * 2 + (lane >> 4) * 16 + wcol * 2);

    auto stage = [&](int kc, int b) {
        uint32_t base = sb + (uint32_t)(b * BUF);
        for (int i = tid; i < 512; i += 256) {
            int r = i >> 2, seg = i & 3;
            uint32_t so = (uint32_t)(r * SA_STR * 2 + seg * 16);
            size_t go = (size_t)r * 1024 + (size_t)kc * 64 + seg * 16;
            cp16(base + SM_AH + so, agh + go);
            cp16(base + SM_AL + so, agl + go);
        }
        for (int i = tid; i < KC * 16; i += 256) {
            int r = i >> 4, seg = i & 15;
            uint32_t so = (uint32_t)(r * SW_STR * 2 + seg * 16);
            size_t go = ((size_t)kc * KC + r) * 1024 + seg * 16;
            cp16(base + SM_WH + so, wgh + go);
            cp16(base + SM_WL + so, wgl + go);
        }
        asm volatile("cp.async.commit_group;" ::: "memory");
    };

    float acc[4][4][4];
#pragma unroll
    for (int mt = 0; mt < 4; mt++)
#pragma unroll
        for (int nt = 0; nt < 4; nt++)
#pragma unroll
            for (int q = 0; q < 4; q++) acc[mt][nt][q] = 0.0f;

    stage(0, 0);
    stage(1, 1);

    for (int kc = 0; kc < NK; kc++) {
        if (kc + 2 < NK) {
            stage(kc + 2, (kc + 2) % 3);
            asm volatile("cp.async.wait_group 2;" ::: "memory");
        } else if (kc + 2 == NK) {
            asm volatile("cp.async.wait_group 1;" ::: "memory");
        } else {
            asm volatile("cp.async.wait_group 0;" ::: "memory");
        }
        __syncthreads();

        uint32_t base = sb + (uint32_t)((kc % 3) * BUF);
#pragma unroll
        for (int s = 0; s < 2; s++) {
            uint32_t soffW = (uint32_t)(s * 16 * SW_STR * 2);
            uint32_t bh0[4], bh1[4], bl0[4], bl1[4];
            ldsm4t(bh0, base + SM_WH + b_base + soffW);
            ldsm4t(bh1, base + SM_WH + b_base + soffW + 32);
            ldsm4t(bl0, base + SM_WL + b_base + soffW);
            ldsm4t(bl1, base + SM_WL + b_base + soffW + 32);
#pragma unroll
            for (int mt = 0; mt < 4; mt++) {
                uint32_t aoff = a_base + (uint32_t)(mt * 16 * SA_STR * 2 + s * 32);
                uint32_t ah[4];
                ldsm4(ah, base + SM_AH + aoff);
                mma_bf16(acc[mt][0], ah, bh0[0], bh0[1]);
                mma_bf16(acc[mt][1], ah, bh0[2], bh0[3]);
                mma_bf16(acc[mt][2], ah, bh1[0], bh1[1]);
                mma_bf16(acc[mt][3], ah, bh1[2], bh1[3]);
                mma_bf16(acc[mt][0], ah, bl0[0], bl0[1]);
                mma_bf16(acc[mt][1], ah, bl0[2], bl0[3]);
                mma_bf16(acc[mt][2], ah, bl1[0], bl1[1]);
                mma_bf16(acc[mt][3], ah, bl1[2], bl1[3]);
                uint32_t al[4];
                ldsm4(al, base + SM_AL + aoff);
                mma_bf16(acc[mt][0], al, bh0[0], bh0[1]);
                mma_bf16(acc[mt][1], al, bh0[2], bh0[3]);
                mma_bf16(acc[mt][2], al, bh1[0], bh1[1]);
                mma_bf16(acc[mt][3], al, bh1[2], bh1[3]);
            }
        }
        __syncthreads();
    }

    // ---- epilogue: ELU(D+bias) -> hi/lo blob ----
    __nv_bfloat16* Oh = (asel == 1) ? g_bBh : g_bAh;   // output flips buffer
    __nv_bfloat16* Ol = (asel == 1) ? g_bBl : g_bAl;
    const int r0 = tile * MT + wrow + (lane >> 2);
    const int cb = nc * NCN + wcol + (lane & 3) * 2;
#pragma unroll
    for (int mt = 0; mt < 4; mt++) {
#pragma unroll
        for (int nt = 0; nt < 4; nt++) {
            int col = cb + nt * 8;
            float b0v = __ldg(&bias[col]), b1v = __ldg(&bias[col + 1]);
#pragma unroll
            for (int h = 0; h < 2; h++) {
                int row = r0 + mt * 16 + h * 8;
                float v0 = eluf(acc[mt][nt][2 * h] + b0v);
                float v1 = eluf(acc[mt][nt][2 * h + 1] + b1v);
                __nv_bfloat16 h0 = __float2bfloat16(v0);
                __nv_bfloat16 h1 = __float2bfloat16(v1);
                __nv_bfloat16 l0 = __float2bfloat16(v0 - __bfloat162float(h0));
                __nv_bfloat16 l1 = __float2bfloat16(v1 - __bfloat162float(h1));
                *(uint32_t*)&Oh[(size_t)row * HID + col] = pkbf(h0, h1);
                *(uint32_t*)&Ol[(size_t)row * HID + col] = pkbf(l0, l1);
            }
        }
    }
}

// ---------------- GEMM3: old row-layout kernel (NCN=160, MODE fp32 out) ----------------
__global__ void __launch_bounds__(256) gemm3_mma(int layer, const float* __restrict__ bias,
                                                 int bias_n)
{
    extern __shared__ char smem[];
    constexpr int KC = 32;
    constexpr int NCN = DOUTP;
    constexpr int SA_STR = 40;
    constexpr int SW_STR = NCN + 8;            // 168
    constexpr int A_BYTES = 128 * SA_STR * 2;
    constexpr int W_BYTES = KC * SW_STR * 2;
    constexpr int SM_AH = 0;
    constexpr int SM_AL = A_BYTES;
    constexpr int SM_WH = 2 * A_BYTES;
    constexpr int SM_WL = 2 * A_BYTES + W_BYTES;
    constexpr int BUF = 2 * A_BYTES + 2 * W_BYTES;
    constexpr int NTILE = NCN / 8;             // 20
    constexpr int WSEG = NCN / 8;              // 20
    constexpr int NK = 16;

    const int tid = threadIdx.x, wid = tid >> 5, lane = tid & 31;
    const int tile = blockIdx.x;
    uint32_t sb = smem_u32(smem);

    const __nv_bfloat16* Wh = g_w3h + (size_t)layer * 512 * DOUTP;
    const __nv_bfloat16* Wl = g_w3l + (size_t)layer * 512 * DOUTP;
    const char* agh = (const char*)(g_bAh + (size_t)tile * MT * 512);
    const char* agl = (const char*)(g_bAl + (size_t)tile * MT * 512);
    const char* wgh = (const char*)Wh;
    const char* wgl = (const char*)Wl;

    const uint32_t a_off = (uint32_t)((wid * 16 + (lane & 15)) * SA_STR * 2 + (lane >> 4) * 16);
    const uint32_t b_off = (uint32_t)((lane & 15) * SW_STR * 2 + (lane >> 4) * 16);

    auto stage = [&](int kc, int b) {
        uint32_t base = sb + (uint32_t)(b * BUF);
        for (int i = tid; i < 512; i += 256) {
            int r = i >> 2, seg = i & 3;
            uint32_t so = (uint32_t)(r * SA_STR * 2 + seg * 16);
            size_t go = (size_t)r * 1024 + (size_t)kc * 64 + seg * 16;
            cp16(base + SM_AH + so, agh + go);
            cp16(base + SM_AL + so, agl + go);
        }
        for (int i = tid; i < KC * WSEG; i += 256) {
            int r = i / WSEG, seg = i % WSEG;
            uint32_t so = (uint32_t)(r * SW_STR * 2 + seg * 16);
            size_t go = ((size_t)kc * KC + r) * (DOUTP * 2) + seg * 16;
            cp16(base + SM_WH + so, wgh + go);
            cp16(base + SM_WL + so, wgl + go);
        }
        asm volatile("cp.async.commit_group;" ::: "memory");
    };

    float acc[NTILE][4];
#pragma unroll
    for (int t = 0; t < NTILE; t++)
#pragma unroll
        for (int q = 0; q < 4; q++) acc[t][q] = 0.0f;

    stage(0, 0);
    stage(1, 1);

    for (int kc = 0; kc < NK; kc++) {
        if (kc + 2 < NK) {
            stage(kc + 2, (kc + 2) % 3);
            asm volatile("cp.async.wait_group 2;" ::: "memory");
        } else if (kc + 2 == NK) {
            asm volatile("cp.async.wait_group 1;" ::: "memory");
        } else {
            asm volatile("cp.async.wait_group 0;" ::: "memory");
        }
        __syncthreads();

        uint32_t base = sb + (uint32_t)((kc % 3) * BUF);
#pragma unroll
        for (int s = 0; s < 2; s++) {
            uint32_t ahr[4], alr[4];
            ldsm4(ahr, base + SM_AH + a_off + s * 32);
            ldsm4(alr, base + SM_AL + a_off + s * 32);
            uint32_t brow = b_off + (uint32_t)(s * 16 * SW_STR * 2);
#pragma unroll
            for (int jb = 0; jb < NTILE / 2; jb++) {
                uint32_t bh[4], bl[4];
                ldsm4t(bh, base + SM_WH + brow + jb * 32);
                ldsm4t(bl, base + SM_WL + brow + jb * 32);
                mma_bf16(acc[2 * jb],     ahr, bh[0], bh[1]);
                mma_bf16(acc[2 * jb],     ahr, bl[0], bl[1]);
                mma_bf16(acc[2 * jb],     alr, bh[0], bh[1]);
                mma_bf16(acc[2 * jb + 1], ahr, bh[2], bh[3]);
                mma_bf16(acc[2 * jb + 1], ahr, bl[2], bl[3]);
                mma_bf16(acc[2 * jb + 1], alr, bh[2], bh[3]);
            }
        }
        __syncthreads();
    }

    const int r0 = tile * MT + wid * 16 + (lane >> 2);
    const int cbase = (lane & 3) * 2;
#pragma unroll
    for (int t = 0; t < NTILE; t++) {
        int col = cbase + t * 8;
        float b0 = (col < bias_n) ? __ldg(&bias[col]) : 0.0f;
        float b1 = (col + 1 < bias_n) ? __ldg(&bias[col + 1]) : 0.0f;
#pragma unroll
        for (int h = 0; h < 2; h++) {
            int row = r0 + h * 8;
            g_params[(size_t)row * DOUTP + col]     = acc[t][2 * h] + b0;
            g_params[(size_t)row * DOUTP + col + 1] = acc[t][2 * h + 1] + b1;
        }
    }
}

// ---------------- spline + permutation ----------------
__global__ void spline_kernel(const int* __restrict__ perms, int layer) {
    int m = blockIdx.x * blockDim.x + threadIdx.x;
    if (m >= MTOT) return;
    const float* pall = &g_params[(size_t)m * DOUTP];
    float cat[12];
#pragma unroll
    for (int j = 0; j < D_HALF; j++) cat[j] = g_x[m * 12 + j];
    float ldsum = 0.0f;
#pragma unroll
    for (int d = 0; d < D_HALF; d++) {
        const float* p = pall + d * SPP;
        float e[KBINS];
        float mx = p[0];
#pragma unroll
        for (int i = 1; i < KBINS; i++) mx = fmaxf(mx, p[i]);
        float s = 0.0f;
#pragma unroll
        for (int i = 0; i < KBINS; i++) { e[i] = expf(p[i] - mx); s += e[i]; }
        float inv = 1.0f / s;
        float cw[KBINS + 1];
        cw[0] = -BVAL;
        {
            float run = 0.0f;
#pragma unroll
            for (int i = 0; i < KBINS - 1; i++) {
                run += 0.001f + 0.992f * e[i] * inv;
                cw[i + 1] = 2.0f * BVAL * run - BVAL;
            }
        }
        cw[KBINS] = BVAL;
        mx = p[KBINS];
#pragma unroll
        for (int i = 1; i < KBINS; i++) mx = fmaxf(mx, p[KBINS + i]);
        s = 0.0f;
#pragma unroll
        for (int i = 0; i < KBINS; i++) { e[i] = expf(p[KBINS + i] - mx); s += e[i]; }
        inv = 1.0f / s;
        float chn[KBINS + 1];
        chn[0] = -BVAL;
        {
            float run = 0.0f;
#pragma unroll
            for (int i = 0; i < KBINS - 1; i++) {
                run += 0.001f + 0.992f * e[i] * inv;
                chn[i + 1] = 2.0f * BVAL * run - BVAL;
            }
        }
        chn[KBINS] = BVAL;
        float dv[KBINS + 1];
        dv[0] = 1.0f; dv[KBINS] = 1.0f;
#pragma unroll
        for (int i = 1; i < KBINS; i++) dv[i] = 0.001f + softplusf(p[2 * KBINS + i - 1]);

        float x = g_x[m * 12 + D_HALF + d];
        float xc = fminf(fmaxf(x, -BVAL), BVAL);
        int idx = 0;
#pragma unroll
        for (int i = 1; i < KBINS; i++) idx += (xc >= cw[i]) ? 1 : 0;
        float icw = cw[idx], iw = cw[idx + 1] - cw[idx];
        float ich = chn[idx], ih = chn[idx + 1] - chn[idx];
        float delta = ih / iw;
        float d0 = dv[idx], d1 = dv[idx + 1];
        float th = (xc - icw) / iw;
        float t1m = th * (1.0f - th);
        float num = ih * (delta * th * th + d0 * t1m);
        float den = delta + (d0 + d1 - 2.0f * delta) * t1m;
        float o = ich + num / den;
        float omt = 1.0f - th;
        float dnum = delta * delta * (d1 * th * th + 2.0f * delta * t1m + d0 * omt * omt);
        float lad = logf(dnum) - 2.0f * logf(den);
        bool inside = (x >= -BVAL) && (x <= BVAL);
        cat[D_HALF + d] = inside ? o : x;
        ldsum += inside ? lad : 0.0f;
    }
    g_ld[m] += ldsum;
    if (layer < LAYERS - 1) {
        float xn[12];
#pragma unroll
        for (int j = 0; j < 12; j++) xn[j] = cat[perms[layer * 12 + j]];
#pragma unroll
        for (int j = 0; j < 12; j++) g_x[m * 12 + j] = xn[j];
    } else {
#pragma unroll
        for (int j = 0; j < 12; j++) g_x[m * 12 + j] = cat[j];
    }
}

__global__ void final_kernel(float* __restrict__ out) {
    int m = blockIdx.x * blockDim.x + threadIdx.x;
    if (m >= MTOT) return;
#pragma unroll
    for (int j = 0; j < 12; j++) out[m * 12 + j] = g_x[m * 12 + j];
    out[(size_t)MTOT * 12 + m] = g_ld[m];
}

// ---------------- host ----------------
extern "C" void kernel_launch(void* const* d_in, const int* in_sizes, int n_in,
                              void* d_out, int out_size)
{
    const float* z  = (const float*)d_in[0];
    const float* c  = (const float*)d_in[1];
    const float* W0 = (const float*)d_in[2];
    const float* b0 = (const float*)d_in[3];
    const float* W1 = (const float*)d_in[4];
    const float* b1 = (const float*)d_in[5];
    const float* W2 = (const float*)d_in[6];
    const float* b2 = (const float*)d_in[7];
    const float* W3 = (const float*)d_in[8];
    const float* b3 = (const float*)d_in[9];
    const int* perms = (const int*)d_in[10];

    const int SM_G12 = 3 * (2 * (128 * 40 * 2) + 2 * (32 * 136 * 2));  // 113,664
    const int SM_G3  = 3 * (2 * (128 * 40 * 2) + 2 * (32 * 168 * 2));  // 125,952
    cudaFuncSetAttribute(gemm_mma24, cudaFuncAttributeMaxDynamicSharedMemorySize, SM_G12);
    cudaFuncSetAttribute(gemm3_mma,  cudaFuncAttributeMaxDynamicSharedMemorySize, SM_G3);

    prep_weights<<<2048, 256>>>(W1, W2, W3);
    init_state<<<MTOT / 256, 256>>>(z);
    dim3 g12(MTILES, 4);
    for (int l = 0; l < LAYERS; l++) {
        gemm0_simt<<<MTOT / 32, 256>>>(W0, b0, c, l);
        gemm_mma24<<<g12, 256, SM_G12>>>(1, 1, l, b1 + l * 512);   // g_bA -> g_bB
        gemm_mma24<<<g12, 256, SM_G12>>>(2, 2, l, b2 + l * 512);   // g_bB -> g_bA
        gemm3_mma<<<MTILES, 256, SM_G3>>>(l, b3 + l * DOUT, DOUT); // g_bA -> params
        spline_kernel<<<MTOT / 256, 256>>>(perms, l);
    }
    final_kernel<<<MTOT / 256, 256>>>((float*)d_out);
}

// round 11
// speedup vs baseline: 2.6277x; 1.0133x over previous
#include <cuda_runtime.h>
#include <cuda_bf16.h>
#include <math.h>
#include <stdint.h>

#define LAYERS  8
#define MTOT    32768
#define MT      128
#define MTILES  (MTOT / MT)      // 256
#define HID     512
#define DINR    22
#define DOUT    138
#define DOUTP   160
#define KBINS   8
#define BVAL    3.0f
#define D_HALF  6
#define SPP     23

// ---------------- device global scratch ----------------
__device__ __nv_bfloat16 g_w1h[LAYERS * 512 * 512];
__device__ __nv_bfloat16 g_w1l[LAYERS * 512 * 512];
__device__ __nv_bfloat16 g_w2h[LAYERS * 512 * 512];
__device__ __nv_bfloat16 g_w2l[LAYERS * 512 * 512];
__device__ __nv_bfloat16 g_w3h[LAYERS * 512 * DOUTP];
__device__ __nv_bfloat16 g_w3l[LAYERS * 512 * DOUTP];
__device__ __nv_bfloat16 g_bAh[MTOT * HID];
__device__ __nv_bfloat16 g_bAl[MTOT * HID];
__device__ __nv_bfloat16 g_bBh[MTOT * HID];
__device__ __nv_bfloat16 g_bBl[MTOT * HID];
__device__ float g_params[(size_t)MTOT * DOUTP];
__device__ float g_x[MTOT * 12];
__device__ float g_ld[MTOT];

// ---------------- helpers ----------------
__device__ __forceinline__ float eluf(float v) { return v > 0.0f ? v : expm1f(v); }
__device__ __forceinline__ float softplusf(float v) { return v > 20.0f ? v : log1pf(expf(v)); }

__device__ __forceinline__ uint32_t smem_u32(const void* p) {
    uint32_t a;
    asm("{ .reg .u64 t; cvta.to.shared.u64 t, %1; cvt.u32.u64 %0, t; }" : "=r"(a) : "l"(p));
    return a;
}
__device__ __forceinline__ uint32_t pkbf(__nv_bfloat16 a, __nv_bfloat16 b) {
    return (uint32_t)__bfloat16_as_ushort(a) | ((uint32_t)__bfloat16_as_ushort(b) << 16);
}
__device__ __forceinline__ void cp16(uint32_t sdst, const void* gsrc) {
    asm volatile("cp.async.cg.shared.global [%0], [%1], 16;" :: "r"(sdst), "l"(gsrc));
}
__device__ __forceinline__ void ldsm4(uint32_t* r, uint32_t a) {
    asm volatile("ldmatrix.sync.aligned.m8n8.x4.shared.b16 {%0,%1,%2,%3}, [%4];"
                 : "=r"(r[0]), "=r"(r[1]), "=r"(r[2]), "=r"(r[3]) : "r"(a));
}
__device__ __forceinline__ void ldsm4t(uint32_t* r, uint32_t a) {
    asm volatile("ldmatrix.sync.aligned.m8n8.x4.trans.shared.b16 {%0,%1,%2,%3}, [%4];"
                 : "=r"(r[0]), "=r"(r[1]), "=r"(r[2]), "=r"(r[3]) : "r"(a));
}
__device__ __forceinline__ void mma_bf16(float* d, const uint32_t* a, uint32_t b0, uint32_t b1) {
    asm volatile(
        "mma.sync.aligned.m16n8k16.row.col.f32.bf16.bf16.f32 "
        "{%0,%1,%2,%3}, {%4,%5,%6,%7}, {%8,%9}, {%0,%1,%2,%3};"
        : "+f"(d[0]), "+f"(d[1]), "+f"(d[2]), "+f"(d[3])
        : "r"(a[0]), "r"(a[1]), "r"(a[2]), "r"(a[3]), "r"(b0), "r"(b1));
}

// ---------------- prep: W1/W2/W3 -> bf16 hi/lo k-major blobs ----------------
__global__ void prep_weights(const float* __restrict__ W1, const float* __restrict__ W2,
                             const float* __restrict__ W3) {
    const long N1 = (long)LAYERS * 512 * 512;
    const long N3 = (long)LAYERS * 512 * DOUTP;
    const long TOT = 2 * N1 + N3;
    for (long i = (long)blockIdx.x * blockDim.x + threadIdx.x; i < TOT;
         i += (long)gridDim.x * blockDim.x) {
        float v; long dst; __nv_bfloat16 *ph, *pl;
        if (i < N1) {
            v = W1[i]; dst = i; ph = g_w1h; pl = g_w1l;
        } else if (i < 2 * N1) {
            long e = i - N1;
            v = W2[e]; dst = e; ph = g_w2h; pl = g_w2l;
        } else {
            long e = i - 2 * N1;
            long l = e / (512L * DOUTP), r = e % (512L * DOUTP);
            int k = (int)(r / DOUTP), n = (int)(r % DOUTP);
            v = (n < DOUT) ? W3[(l * 512 + k) * DOUT + n] : 0.0f;
            dst = e; ph = g_w3h; pl = g_w3l;
        }
        __nv_bfloat16 hi = __float2bfloat16(v);
        __nv_bfloat16 lo = __float2bfloat16(v - __bfloat162float(hi));
        ph[dst] = hi; pl[dst] = lo;
    }
}

__global__ void init_state(const float* __restrict__ z) {
    int m = blockIdx.x * blockDim.x + threadIdx.x;
    if (m >= MTOT) return;
    g_ld[m] = 0.0f;
#pragma unroll
    for (int j = 0; j < 12; j++) g_x[m * 12 + j] = z[m * 12 + j];
}

// ---------------- GEMM0: SIMT fp32 (K=22), writes g_bA hi/lo blob ----------------
__global__ void __launch_bounds__(256) gemm0_simt(const float* __restrict__ W0,
                                                  const float* __restrict__ b0,
                                                  const float* __restrict__ c, int layer)
{
    __shared__ float inp_t[DINR][32];
    const int tid = threadIdx.x;
    const int row0 = blockIdx.x * 32;
    for (int i = tid; i < DINR * 32; i += 256) {
        int k = i >> 5, r = i & 31;
        int m = row0 + r;
        inp_t[k][r] = (k < D_HALF) ? g_x[m * 12 + k] : c[(size_t)m * 16 + (k - D_HALF)];
    }
    __syncthreads();

    const float* W = W0 + (size_t)layer * DINR * 512;
    const int j0 = tid * 2;
    float a0[32], a1[32];
#pragma unroll
    for (int r = 0; r < 32; r++) { a0[r] = 0.0f; a1[r] = 0.0f; }
#pragma unroll
    for (int k = 0; k < DINR; k++) {
        float2 w = *(const float2*)(W + (size_t)k * 512 + j0);
#pragma unroll
        for (int r = 0; r < 32; r++) {
            float hv = inp_t[k][r];
            a0[r] = fmaf(hv, w.x, a0[r]);
            a1[r] = fmaf(hv, w.y, a1[r]);
        }
    }
    float2 bv = *(const float2*)(b0 + (size_t)layer * 512 + j0);
#pragma unroll
    for (int r = 0; r < 32; r++) {
        float v0 = eluf(a0[r] + bv.x);
        float v1 = eluf(a1[r] + bv.y);
        __nv_bfloat16 h0 = __float2bfloat16(v0);
        __nv_bfloat16 h1 = __float2bfloat16(v1);
        __nv_bfloat16 l0 = __float2bfloat16(v0 - __bfloat162float(h0));
        __nv_bfloat16 l1 = __float2bfloat16(v1 - __bfloat162float(h1));
        size_t off = (size_t)(row0 + r) * HID + j0;
        *(uint32_t*)&g_bAh[off] = pkbf(h0, h1);
        *(uint32_t*)&g_bAl[off] = pkbf(l0, l1);
    }
}

// ---------------- GEMM1/2: mma.sync bf16x3, warp tile 2x4, KC=32 ----------------
// Single barrier per chunk (wait -> sync -> stage -> compute); term-major MMA order.
__global__ void __launch_bounds__(256, 2) gemm_mma24(int asel, int layer_base_sel,
                                                     int layer,
                                                     const float* __restrict__ bias)
{
    extern __shared__ char smem[];
    constexpr int KC = 32;
    constexpr int NCN = 128;
    constexpr int SA_STR = 40;                 // 80B rows
    constexpr int SW_STR = NCN + 8;            // 272B rows
    constexpr int A_BYTES = 128 * SA_STR * 2;  // 10240
    constexpr int W_BYTES = KC * SW_STR * 2;   // 8704
    constexpr int SM_AH = 0;
    constexpr int SM_AL = A_BYTES;
    constexpr int SM_WH = 2 * A_BYTES;
    constexpr int SM_WL = 2 * A_BYTES + W_BYTES;
    constexpr int BUF = 2 * A_BYTES + 2 * W_BYTES;
    constexpr int NK = 512 / KC;               // 16

    const int tid = threadIdx.x, wid = tid >> 5, lane = tid & 31;
    const int tile = blockIdx.x;
    const int nc = blockIdx.y;
    uint32_t sb = smem_u32(smem);

    const __nv_bfloat16* Ah = (asel == 1) ? g_bAh : g_bBh;
    const __nv_bfloat16* Al = (asel == 1) ? g_bAl : g_bBl;
    const __nv_bfloat16* Wh = ((layer_base_sel == 1) ? g_w1h : g_w2h) + (size_t)layer * 512 * 512;
    const __nv_bfloat16* Wl = ((layer_base_sel == 1) ? g_w1l : g_w2l) + (size_t)layer * 512 * 512;

    const char* agh = (const char*)(Ah + (size_t)tile * MT * 512);
    const char* agl = (const char*)(Al + (size_t)tile * MT * 512);
    const char* wgh = (const char*)(Wh + (size_t)nc * NCN);
    const char* wgl = (const char*)(Wl + (size_t)nc * NCN);

    const int wrow = (wid & 1) * 64;
    const int wcol = (wid >> 1) * 32;
    const uint32_t a_base = (uint32_t)((wrow + (lane & 15)) * SA_STR * 2 + (lane >> 4) * 16);
    const uint32_t b_base = (uint32_t)((lane & 15) * SW_STR * 2 + (lane >> 4) * 16 + wcol * 2);

    auto stage = [&](int kc, int b) {
        uint32_t base = sb + (uint32_t)(b * BUF);
        for (int i = tid; i < 512; i += 256) {
            int r = i >> 2, seg = i & 3;
            uint32_t so = (uint32_t)(r * SA_STR * 2 + seg * 16);
            size_t go = (size_t)r * 1024 + (size_t)kc * 64 + seg * 16;
            cp16(base + SM_AH + so, agh + go);
            cp16(base + SM_AL + so, agl + go);
        }
        for (int i = tid; i < KC * 16; i += 256) {
            int r = i >> 4, seg = i & 15;
            uint32_t so = (uint32_t)(r * SW_STR * 2 + seg * 16);
            size_t go = ((size_t)kc * KC + r) * 1024 + seg * 16;
            cp16(base + SM_WH + so, wgh + go);
            cp16(base + SM_WL + so, wgl + go);
        }
        asm volatile("cp.async.commit_group;" ::: "memory");
    };

    float acc[4][4][4];
#pragma unroll
    for (int mt = 0; mt < 4; mt++)
#pragma unroll
        for (int nt = 0; nt < 4; nt++)
#pragma unroll
            for (int q = 0; q < 4; q++) acc[mt][nt][q] = 0.0f;

    stage(0, 0);
    stage(1, 1);

    for (int kc = 0; kc < NK; kc++) {
        if (kc < NK - 1) {
            asm volatile("cp.async.wait_group 1;" ::: "memory");
        } else {
            asm volatile("cp.async.wait_group 0;" ::: "memory");
        }
        __syncthreads();                       // single barrier per chunk
        if (kc + 2 < NK) stage(kc + 2, (kc + 2) % 3);   // writes (kc-1)%3: safe

        uint32_t base = sb + (uint32_t)((kc % 3) * BUF);
#pragma unroll
        for (int s = 0; s < 2; s++) {
            uint32_t soffW = (uint32_t)(s * 16 * SW_STR * 2);
            uint32_t bh0[4], bh1[4], bl0[4], bl1[4];
            ldsm4t(bh0, base + SM_WH + b_base + soffW);
            ldsm4t(bh1, base + SM_WH + b_base + soffW + 32);
            ldsm4t(bl0, base + SM_WL + b_base + soffW);
            ldsm4t(bl1, base + SM_WL + b_base + soffW + 32);
            uint32_t ah[4][4];
#pragma unroll
            for (int mt = 0; mt < 4; mt++)
                ldsm4(ah[mt], base + SM_AH + a_base + (uint32_t)(mt * 16 * SA_STR * 2 + s * 32));
            // term 1: Ah x Wh  (16 independent MMAs)
#pragma unroll
            for (int mt = 0; mt < 4; mt++) {
                mma_bf16(acc[mt][0], ah[mt], bh0[0], bh0[1]);
                mma_bf16(acc[mt][1], ah[mt], bh0[2], bh0[3]);
                mma_bf16(acc[mt][2], ah[mt], bh1[0], bh1[1]);
                mma_bf16(acc[mt][3], ah[mt], bh1[2], bh1[3]);
            }
            // term 2: Ah x Wl
#pragma unroll
            for (int mt = 0; mt < 4; mt++) {
                mma_bf16(acc[mt][0], ah[mt], bl0[0], bl0[1]);
                mma_bf16(acc[mt][1], ah[mt], bl0[2], bl0[3]);
                mma_bf16(acc[mt][2], ah[mt], bl1[0], bl1[1]);
                mma_bf16(acc[mt][3], ah[mt], bl1[2], bl1[3]);
            }
            // term 3: Al x Wh
            uint32_t al[4][4];
#pragma unroll
            for (int mt = 0; mt < 4; mt++)
                ldsm4(al[mt], base + SM_AL + a_base + (uint32_t)(mt * 16 * SA_STR * 2 + s * 32));
#pragma unroll
            for (int mt = 0; mt < 4; mt++) {
                mma_bf16(acc[mt][0], al[mt], bh0[0], bh0[1]);
                mma_bf16(acc[mt][1], al[mt], bh0[2], bh0[3]);
                mma_bf16(acc[mt][2], al[mt], bh1[0], bh1[1]);
                mma_bf16(acc[mt][3], al[mt], bh1[2], bh1[3]);
            }
        }
    }

    // ---- epilogue: ELU(D+bias) -> hi/lo blob ----
    __nv_bfloat16* Oh = (asel == 1) ? g_bBh : g_bAh;
    __nv_bfloat16* Ol = (asel == 1) ? g_bBl : g_bAl;
    const int r0 = tile * MT + wrow + (lane >> 2);
    const int cb = nc * NCN + wcol + (lane & 3) * 2;
#pragma unroll
    for (int mt = 0; mt < 4; mt++) {
#pragma unroll
        for (int nt = 0; nt < 4; nt++) {
            int col = cb + nt * 8;
            float b0v = __ldg(&bias[col]), b1v = __ldg(&bias[col + 1]);
#pragma unroll
            for (int h = 0; h < 2; h++) {
                int row = r0 + mt * 16 + h * 8;
                float v0 = eluf(acc[mt][nt][2 * h] + b0v);
                float v1 = eluf(acc[mt][nt][2 * h + 1] + b1v);
                __nv_bfloat16 h0 = __float2bfloat16(v0);
                __nv_bfloat16 h1 = __float2bfloat16(v1);
                __nv_bfloat16 l0 = __float2bfloat16(v0 - __bfloat162float(h0));
                __nv_bfloat16 l1 = __float2bfloat16(v1 - __bfloat162float(h1));
                *(uint32_t*)&Oh[(size_t)row * HID + col] = pkbf(h0, h1);
                *(uint32_t*)&Ol[(size_t)row * HID + col] = pkbf(l0, l1);
            }
        }
    }
}

// ---------------- GEMM3 (N=160, fp32 out) with single-barrier pipeline ----------------
__global__ void __launch_bounds__(256) gemm3_mma(int layer, const float* __restrict__ bias,
                                                 int bias_n)
{
    extern __shared__ char smem[];
    constexpr int KC = 32;
    constexpr int NCN = DOUTP;
    constexpr int SA_STR = 40;
    constexpr int SW_STR = NCN + 8;            // 168
    constexpr int A_BYTES = 128 * SA_STR * 2;
    constexpr int W_BYTES = KC * SW_STR * 2;
    constexpr int SM_AH = 0;
    constexpr int SM_AL = A_BYTES;
    constexpr int SM_WH = 2 * A_BYTES;
    constexpr int SM_WL = 2 * A_BYTES + W_BYTES;
    constexpr int BUF = 2 * A_BYTES + 2 * W_BYTES;
    constexpr int NTILE = NCN / 8;             // 20
    constexpr int WSEG = NCN / 8;
    constexpr int NK = 16;

    const int tid = threadIdx.x, wid = tid >> 5, lane = tid & 31;
    const int tile = blockIdx.x;
    uint32_t sb = smem_u32(smem);

    const __nv_bfloat16* Wh = g_w3h + (size_t)layer * 512 * DOUTP;
    const __nv_bfloat16* Wl = g_w3l + (size_t)layer * 512 * DOUTP;
    const char* agh = (const char*)(g_bAh + (size_t)tile * MT * 512);
    const char* agl = (const char*)(g_bAl + (size_t)tile * MT * 512);
    const char* wgh = (const char*)Wh;
    const char* wgl = (const char*)Wl;

    const uint32_t a_off = (uint32_t)((wid * 16 + (lane & 15)) * SA_STR * 2 + (lane >> 4) * 16);
    const uint32_t b_off = (uint32_t)((lane & 15) * SW_STR * 2 + (lane >> 4) * 16);

    auto stage = [&](int kc, int b) {
        uint32_t base = sb + (uint32_t)(b * BUF);
        for (int i = tid; i < 512; i += 256) {
            int r = i >> 2, seg = i & 3;
            uint32_t so = (uint32_t)(r * SA_STR * 2 + seg * 16);
            size_t go = (size_t)r * 1024 + (size_t)kc * 64 + seg * 16;
            cp16(base + SM_AH + so, agh + go);
            cp16(base + SM_AL + so, agl + go);
        }
        for (int i = tid; i < KC * WSEG; i += 256) {
            int r = i / WSEG, seg = i % WSEG;
            uint32_t so = (uint32_t)(r * SW_STR * 2 + seg * 16);
            size_t go = ((size_t)kc * KC + r) * (DOUTP * 2) + seg * 16;
            cp16(base + SM_WH + so, wgh + go);
            cp16(base + SM_WL + so, wgl + go);
        }
        asm volatile("cp.async.commit_group;" ::: "memory");
    };

    float acc[NTILE][4];
#pragma unroll
    for (int t = 0; t < NTILE; t++)
#pragma unroll
        for (int q = 0; q < 4; q++) acc[t][q] = 0.0f;

    stage(0, 0);
    stage(1, 1);

    for (int kc = 0; kc < NK; kc++) {
        if (kc < NK - 1) {
            asm volatile("cp.async.wait_group 1;" ::: "memory");
        } else {
            asm volatile("cp.async.wait_group 0;" ::: "memory");
        }
        __syncthreads();
        if (kc + 2 < NK) stage(kc + 2, (kc + 2) % 3);

        uint32_t base = sb + (uint32_t)((kc % 3) * BUF);
#pragma unroll
        for (int s = 0; s < 2; s++) {
            uint32_t ahr[4], alr[4];
            ldsm4(ahr, base + SM_AH + a_off + s * 32);
            ldsm4(alr, base + SM_AL + a_off + s * 32);
            uint32_t brow = b_off + (uint32_t)(s * 16 * SW_STR * 2);
#pragma unroll
            for (int jb = 0; jb < NTILE / 2; jb++) {
                uint32_t bh[4], bl[4];
                ldsm4t(bh, base + SM_WH + brow + jb * 32);
                ldsm4t(bl, base + SM_WL + brow + jb * 32);
                mma_bf16(acc[2 * jb],     ahr, bh[0], bh[1]);
                mma_bf16(acc[2 * jb + 1], ahr, bh[2], bh[3]);
                mma_bf16(acc[2 * jb],     ahr, bl[0], bl[1]);
                mma_bf16(acc[2 * jb + 1], ahr, bl[2], bl[3]);
                mma_bf16(acc[2 * jb],     alr, bh[0], bh[1]);
                mma_bf16(acc[2 * jb + 1], alr, bh[2], bh[3]);
            }
        }
    }

    const int r0 = tile * MT + wid * 16 + (lane >> 2);
    const int cbase = (lane & 3) * 2;
#pragma unroll
    for (int t = 0; t < NTILE; t++) {
        int col = cbase + t * 8;
        float b0 = (col < bias_n) ? __ldg(&bias[col]) : 0.0f;
        float b1 = (col + 1 < bias_n) ? __ldg(&bias[col + 1]) : 0.0f;
#pragma unroll
        for (int h = 0; h < 2; h++) {
            int row = r0 + h * 8;
            g_params[(size_t)row * DOUTP + col]     = acc[t][2 * h] + b0;
            g_params[(size_t)row * DOUTP + col + 1] = acc[t][2 * h + 1] + b1;
        }
    }
}

// ---------------- spline + permutation ----------------
__global__ void spline_kernel(const int* __restrict__ perms, int layer) {
    int m = blockIdx.x * blockDim.x + threadIdx.x;
    if (m >= MTOT) return;
    const float* pall = &g_params[(size_t)m * DOUTP];
    float cat[12];
#pragma unroll
    for (int j = 0; j < D_HALF; j++) cat[j] = g_x[m * 12 + j];
    float ldsum = 0.0f;
#pragma unroll
    for (int d = 0; d < D_HALF; d++) {
        const float* p = pall + d * SPP;
        float e[KBINS];
        float mx = p[0];
#pragma unroll
        for (int i = 1; i < KBINS; i++) mx = fmaxf(mx, p[i]);
        float s = 0.0f;
#pragma unroll
        for (int i = 0; i < KBINS; i++) { e[i] = expf(p[i] - mx); s += e[i]; }
        float inv = 1.0f / s;
        float cw[KBINS + 1];
        cw[0] = -BVAL;
        {
            float run = 0.0f;
#pragma unroll
            for (int i = 0; i < KBINS - 1; i++) {
                run += 0.001f + 0.992f * e[i] * inv;
                cw[i + 1] = 2.0f * BVAL * run - BVAL;
            }
        }
        cw[KBINS] = BVAL;
        mx = p[KBINS];
#pragma unroll
        for (int i = 1; i < KBINS; i++) mx = fmaxf(mx, p[KBINS + i]);
        s = 0.0f;
#pragma unroll
        for (int i = 0; i < KBINS; i++) { e[i] = expf(p[KBINS + i] - mx); s += e[i]; }
        inv = 1.0f / s;
        float chn[KBINS + 1];
        chn[0] = -BVAL;
        {
            float run = 0.0f;
#pragma unroll
            for (int i = 0; i < KBINS - 1; i++) {
                run += 0.001f + 0.992f * e[i] * inv;
                chn[i + 1] = 2.0f * BVAL * run - BVAL;
            }
        }
        chn[KBINS] = BVAL;
        float dv[KBINS + 1];
        dv[0] = 1.0f; dv[KBINS] = 1.0f;
#pragma unroll
        for (int i = 1; i < KBINS; i++) dv[i] = 0.001f + softplusf(p[2 * KBINS + i - 1]);

        float x = g_x[m * 12 + D_HALF + d];
        float xc = fminf(fmaxf(x, -BVAL), BVAL);
        int idx = 0;
#pragma unroll
        for (int i = 1; i < KBINS; i++) idx += (xc >= cw[i]) ? 1 : 0;
        float icw = cw[idx], iw = cw[idx + 1] - cw[idx];
        float ich = chn[idx], ih = chn[idx + 1] - chn[idx];
        float delta = ih / iw;
        float d0 = dv[idx], d1 = dv[idx + 1];
        float th = (xc - icw) / iw;
        float t1m = th * (1.0f - th);
        float num = ih * (delta * th * th + d0 * t1m);
        float den = delta + (d0 + d1 - 2.0f * delta) * t1m;
        float o = ich + num / den;
        float omt = 1.0f - th;
        float dnum = delta * delta * (d1 * th * th + 2.0f * delta * t1m + d0 * omt * omt);
        float lad = logf(dnum) - 2.0f * logf(den);
        bool inside = (x >= -BVAL) && (x <= BVAL);
        cat[D_HALF + d] = inside ? o : x;
        ldsum += inside ? lad : 0.0f;
    }
    g_ld[m] += ldsum;
    if (layer < LAYERS - 1) {
        float xn[12];
#pragma unroll
        for (int j = 0; j < 12; j++) xn[j] = cat[perms[layer * 12 + j]];
#pragma unroll
        for (int j = 0; j < 12; j++) g_x[m * 12 + j] = xn[j];
    } else {
#pragma unroll
        for (int j = 0; j < 12; j++) g_x[m * 12 + j] = cat[j];
    }
}

__global__ void final_kernel(float* __restrict__ out) {
    int m = blockIdx.x * blockDim.x + threadIdx.x;
    if (m >= MTOT) return;
#pragma unroll
    for (int j = 0; j < 12; j++) out[m * 12 + j] = g_x[m * 12 + j];
    out[(size_t)MTOT * 12 + m] = g_ld[m];
}

// ---------------- host ----------------
extern "C" void kernel_launch(void* const* d_in, const int* in_sizes, int n_in,
                              void* d_out, int out_size)
{
    const float* z  = (const float*)d_in[0];
    const float* c  = (const float*)d_in[1];
    const float* W0 = (const float*)d_in[2];
    const float* b0 = (const float*)d_in[3];
    const float* W1 = (const float*)d_in[4];
    const float* b1 = (const float*)d_in[5];
    const float* W2 = (const float*)d_in[6];
    const float* b2 = (const float*)d_in[7];
    const float* W3 = (const float*)d_in[8];
    const float* b3 = (const float*)d_in[9];
    const int* perms = (const int*)d_in[10];

    const int SM_G12 = 3 * (2 * (128 * 40 * 2) + 2 * (32 * 136 * 2));  // 113,664
    const int SM_G3  = 3 * (2 * (128 * 40 * 2) + 2 * (32 * 168 * 2));  // 125,952
    cudaFuncSetAttribute(gemm_mma24, cudaFuncAttributeMaxDynamicSharedMemorySize, SM_G12);
    cudaFuncSetAttribute(gemm3_mma,  cudaFuncAttributeMaxDynamicSharedMemorySize, SM_G3);

    prep_weights<<<2048, 256>>>(W1, W2, W3);
    init_state<<<MTOT / 256, 256>>>(z);
    dim3 g12(MTILES, 4);
    for (int l = 0; l < LAYERS; l++) {
        gemm0_simt<<<MTOT / 32, 256>>>(W0, b0, c, l);
        gemm_mma24<<<g12, 256, SM_G12>>>(1, 1, l, b1 + l * 512);   // g_bA -> g_bB
        gemm_mma24<<<g12, 256, SM_G12>>>(2, 2, l, b2 + l * 512);   // g_bB -> g_bA
        gemm3_mma<<<MTILES, 256, SM_G3>>>(l, b3 + l * DOUT, DOUT); // g_bA -> params
        spline_kernel<<<MTOT / 256, 256>>>(perms, l);
    }
    final_kernel<<<MTOT / 256, 256>>>((float*)d_out);
}